// round 13
// baseline (speedup 1.0000x reference)
#include <cuda_runtime.h>
#include <math.h>
#include <stdint.h>

#define NPB 65536
#define NT  131072

// ---------------- scratch ----------
__device__ float g_X [NT*64];
__device__ float g_Mk[NT*64];
__device__ float g_Q [NT*64];
__device__ float g_K [NT*64];
__device__ float g_V [NT*64];
__device__ float g_T1[NT*64];
__device__ float g_H1[NT*256];
__device__ float g_H2[NT*256];
__device__ float g_GP[2*128*1152];
__device__ float g_MC[2*64*64];

__device__ __forceinline__ float gelu_f(float u){
    return 0.5f*u*(1.f+erff(u*0.70710678118654752f));
}
__device__ __forceinline__ uint32_t tf32c(float f){
    uint32_t r; asm("cvt.rna.tf32.f32 %0, %1;" : "=r"(r) : "f"(f)); return r;
}
#define MMA_TF32(d, a, b0, b1) \
  asm volatile("mma.sync.aligned.m16n8k8.row.col.f32.tf32.tf32.f32 " \
    "{%0,%1,%2,%3},{%4,%5,%6,%7},{%8,%9},{%0,%1,%2,%3};" \
    : "+f"((d)[0]),"+f"((d)[1]),"+f"((d)[2]),"+f"((d)[3]) \
    : "r"((a)[0]),"r"((a)[1]),"r"((a)[2]),"r"((a)[3]),"r"(b0),"r"(b1))

// ---------------- tf32 tensor GEMM (R7-exact) ------------------------------
// Tile 128px(M) x 64out(N), K=64 per chunk. 128 threads = 4 warps.
#define XS_STRIDE 68
#define WS_STRIDE 72
#define XS_U (128*XS_STRIDE)
#define WS_U (64*WS_STRIDE)
#define TM_SMEM ((XS_U + WS_U + 64)*4)

template<int KC,int NC,int MODE>
__global__ __launch_bounds__(128, 4) void k_tmma(
        const float* __restrict__ X, int xStride,
        const float* __restrict__ W, int wStride, int wBatchStride,
        const float* __restrict__ bias,
        float* __restrict__ OUT, int oStride){
    extern __shared__ uint32_t smu[];
    uint32_t* xs = smu;
    uint32_t* ws = smu + XS_U;
    float*    sb = (float*)(smu + XS_U + WS_U);
    const int t = threadIdx.x;
    const int warp = t>>5, lane = t&31;
    const int lr = lane>>2, lc = lane&3;
    const int m0 = warp*32;
    const size_t tileBase = (size_t)blockIdx.x*128;
    const float* Wb = W + (wBatchStride ? (int)(tileBase>>16)*(size_t)wBatchStride : 0);
    if(bias && t<64) sb[t] = bias[t];

    float acc[64];
    const int CH = (KC>NC)?KC:NC;

    for(int c=0;c<CH;c++){
        const int kOff = (KC>1)? c*64 : 0;
        const int nOff = (NC>1)? c*64 : 0;
        if(c) __syncthreads();
        if(c==0 || KC>1){
            #pragma unroll
            for(int it=0;it<16;it++){
                int s4 = t + it*128;
                int p = s4>>4, c4 = s4&15;
                float4 v = *(const float4*)(X + (tileBase+p)*(size_t)xStride + kOff + c4*4);
                uint32_t* xr = xs + p*XS_STRIDE + c4*4;
                xr[0]=tf32c(v.x); xr[1]=tf32c(v.y); xr[2]=tf32c(v.z); xr[3]=tf32c(v.w);
            }
        }
        #pragma unroll
        for(int it=0;it<32;it++){
            int s = t + it*128;
            int o = s&63, j = s>>6;
            ws[j*WS_STRIDE+o] = tf32c(Wb[(size_t)(kOff+j)*wStride + nOff + o]);
        }
        __syncthreads();
        if(c==0 || NC>1){
            if(bias){
                #pragma unroll
                for(int mt=0;mt<2;mt++)
                    #pragma unroll
                    for(int j=0;j<8;j++){
                        float b0 = sb[j*8 + 2*lc], b1 = sb[j*8 + 2*lc + 1];
                        acc[mt*32+j*4+0]=b0; acc[mt*32+j*4+1]=b1;
                        acc[mt*32+j*4+2]=b0; acc[mt*32+j*4+3]=b1;
                    }
            } else {
                #pragma unroll
                for(int q=0;q<64;q++) acc[q]=0.f;
            }
        }
        #pragma unroll
        for(int k0=0;k0<64;k0+=8){
            uint32_t a[2][4];
            #pragma unroll
            for(int mt=0;mt<2;mt++){
                const uint32_t* xbp = xs + (m0+mt*16+lr)*XS_STRIDE + k0 + lc;
                a[mt][0]=xbp[0]; a[mt][1]=xbp[8*XS_STRIDE];
                a[mt][2]=xbp[4]; a[mt][3]=xbp[8*XS_STRIDE+4];
            }
            #pragma unroll
            for(int j=0;j<8;j++){
                uint32_t b0 = ws[(k0+lc  )*WS_STRIDE + j*8 + lr];
                uint32_t b1 = ws[(k0+lc+4)*WS_STRIDE + j*8 + lr];
                MMA_TF32(acc +      j*4, a[0], b0, b1);
                MMA_TF32(acc + 32 + j*4, a[1], b0, b1);
            }
        }
        if(NC>1 || c==CH-1){
            #pragma unroll
            for(int mt=0;mt<2;mt++){
                #pragma unroll
                for(int j=0;j<8;j++){
                    size_t row = tileBase + m0 + mt*16 + lr;
                    int col = nOff + j*8 + 2*lc;
                    float v0=acc[mt*32+j*4], v1=acc[mt*32+j*4+1];
                    float v2=acc[mt*32+j*4+2], v3=acc[mt*32+j*4+3];
                    if(MODE==1){ v0=gelu_f(v0); v1=gelu_f(v1); v2=gelu_f(v2); v3=gelu_f(v3); }
                    float* p0 = OUT + row*(size_t)oStride + col;
                    float* p8 = p0 + 8*(size_t)oStride;
                    if(MODE==2){
                        float2 o0 = *(float2*)p0, o8 = *(float2*)p8;
                        v0+=o0.x; v1+=o0.y; v2+=o8.x; v3+=o8.y;
                    }
                    *(float2*)p0 = make_float2(v0,v1);
                    *(float2*)p8 = make_float2(v2,v3);
                }
            }
        }
    }
}

// ---------------- gram partials via mma tf32 (validated R12) ---------------
#define GR_STRIDE 68
__global__ __launch_bounds__(256) void k_gram(const float* __restrict__ Q,
        const float* __restrict__ K, float* __restrict__ gpart){
    __shared__ float sq[64*GR_STRIDE], sk[64*GR_STRIDE];
    const int t=threadIdx.x, warp=t>>5, lane=t&31;
    const int lr=lane>>2, lc=lane&3;
    const int b=blockIdx.y;
    const int h = warp&3;
    const int nb = (warp&1)*32;
    float accS[8];
    #pragma unroll
    for(int i=0;i<8;i++) accS[i]=0.f;
    float nrm=0.f;

    for(int ch=0; ch<8; ch++){
        size_t base = ((size_t)b*NPB + (size_t)blockIdx.x*512 + ch*64)*64;
        __syncthreads();
        #pragma unroll
        for(int it=0; it<4; it++){
            int s4 = t + it*256;
            int p = s4>>4, c4 = s4&15;
            float4 v = *(const float4*)(Q + base + p*64 + c4*4);
            float* r = sq + p*GR_STRIDE + c4*4;
            r[0]=v.x; r[1]=v.y; r[2]=v.z; r[3]=v.w;
            float4 w = *(const float4*)(K + base + p*64 + c4*4);
            float* r2 = sk + p*GR_STRIDE + c4*4;
            r2[0]=w.x; r2[1]=w.y; r2[2]=w.z; r2[3]=w.w;
        }
        __syncthreads();
        if(warp<4){
            #pragma unroll
            for(int k0=0;k0<64;k0+=8){
                uint32_t a[4];
                a[0]=tf32c(sk[(k0+lc  )*GR_STRIDE + h*16+lr  ]);
                a[1]=tf32c(sk[(k0+lc  )*GR_STRIDE + h*16+lr+8]);
                a[2]=tf32c(sk[(k0+lc+4)*GR_STRIDE + h*16+lr  ]);
                a[3]=tf32c(sk[(k0+lc+4)*GR_STRIDE + h*16+lr+8]);
                #pragma unroll
                for(int nt=0;nt<2;nt++){
                    uint32_t b0=tf32c(sq[(k0+lc  )*GR_STRIDE + h*16+nt*8+lr]);
                    uint32_t b1=tf32c(sq[(k0+lc+4)*GR_STRIDE + h*16+nt*8+lr]);
                    MMA_TF32(accS+nt*4, a, b0, b1);
                }
            }
        } else {
            const float* s = (warp<6)? sq : sk;
            int c = nb + lane;
            #pragma unroll 8
            for(int p=0;p<64;p++){ float v=s[p*GR_STRIDE+c]; nrm += v*v; }
        }
    }
    float* gp = gpart + ((size_t)b*128 + blockIdx.x)*1152;
    if(warp<4){
        float* gs = gp + h*256;
        #pragma unroll
        for(int nt=0;nt<2;nt++){
            int e0 = nt*8 + 2*lc;
            gs[lr*16 + e0]       = accS[nt*4+0];
            gs[lr*16 + e0+1]     = accS[nt*4+1];
            gs[(lr+8)*16 + e0]   = accS[nt*4+2];
            gs[(lr+8)*16 + e0+1] = accS[nt*4+3];
        }
    } else {
        int off = (warp<6)? 1024 : 1088;
        gp[off + nb + lane] = nrm;
    }
}

// ---------------- attn softmax + fold into Mcomb ---------------------------
__global__ __launch_bounds__(256) void k_attn(const float* __restrict__ gpart,
        const float* __restrict__ Wp, const float* __restrict__ resc,
        float* __restrict__ Mcomb){
    __shared__ float sred[2304];
    __shared__ float sa[2048];
    int tid = threadIdx.x;
    for(int jj=tid;jj<2304;jj+=256){
        int b=jj/1152, j=jj-b*1152;
        float acc=0.f;
        for(int blk=0;blk<128;blk++) acc += gpart[((size_t)b*128+blk)*1152 + j];
        sred[jj]=acc;
    }
    __syncthreads();
    if(tid<128){
        int b=tid>>6, hd=tid&63, h=hd>>4, d=hd&15;
        float nk = fmaxf(sqrtf(sred[b*1152+1088+hd]),1e-6f);
        float r = resc[h];
        float row[16]; float mx=-1e30f;
        #pragma unroll
        for(int e=0;e<16;e++){
            float nq = fmaxf(sqrtf(sred[b*1152+1024+h*16+e]),1e-6f);
            float v = sred[b*1152 + h*256 + d*16 + e] / (nk*nq) * r;
            row[e]=v; mx=fmaxf(mx,v);
        }
        float s=0.f;
        #pragma unroll
        for(int e=0;e<16;e++){ row[e]=expf(row[e]-mx); s+=row[e]; }
        float inv=1.f/s;
        #pragma unroll
        for(int e=0;e<16;e++) sa[((b*4+h)*16+d)*16+e] = row[e]*inv;
    }
    __syncthreads();
    for(int job=tid;job<8192;job+=256){
        int b=job>>12, rem=job&4095, ci=rem>>6, co=rem&63;
        int h=ci>>4, e=ci&15;
        float acc=0.f;
        #pragma unroll
        for(int d=0;d<16;d++) acc += sa[((b*4+h)*16+d)*16+e] * Wp[(h*16+d)*64+co];
        Mcomb[job]=acc;
    }
}

// ---------------- transposes ----------------
__global__ __launch_bounds__(256) void k_nchw2nhwc(const float* __restrict__ in, float* __restrict__ out){
    __shared__ float t[32][33];
    int tx = threadIdx.x & 31, ty = threadIdx.x >> 5;
    int pt = blockIdx.x, ct = blockIdx.y, b = blockIdx.z;
    const float* ip = in  + (size_t)b*64*NPB;
    float*       op = out + (size_t)b*NPB*64;
    #pragma unroll
    for(int r=0;r<4;r++){
        int c = ct*32 + ty + r*8;
        t[ty+r*8][tx] = ip[(size_t)c*NPB + (size_t)pt*32 + tx];
    }
    __syncthreads();
    #pragma unroll
    for(int r=0;r<4;r++){
        int p = pt*32 + ty + r*8;
        op[(size_t)p*64 + ct*32 + tx] = t[tx][ty+r*8];
    }
}
__global__ __launch_bounds__(256) void k_nhwc2nchw(const float* __restrict__ in, float* __restrict__ out){
    __shared__ float t[32][33];
    int tx = threadIdx.x & 31, ty = threadIdx.x >> 5;
    int pt = blockIdx.x, ct = blockIdx.y, b = blockIdx.z;
    const float* ip = in  + (size_t)b*NPB*64;
    float*       op = out + (size_t)b*64*NPB;
    #pragma unroll
    for(int r=0;r<4;r++){
        int p = pt*32 + ty + r*8;
        t[ty+r*8][tx] = ip[(size_t)p*64 + ct*32 + tx];
    }
    __syncthreads();
    #pragma unroll
    for(int r=0;r<4;r++){
        int c = ct*32 + ty + r*8;
        op[(size_t)c*NPB + (size_t)pt*32 + tx] = t[tx][ty+r*8];
    }
}

// ---------------- coalesced LayerNorm --------------------------------------
__global__ __launch_bounds__(256) void k_ln(const float* __restrict__ X,
        const float* __restrict__ g, const float* __restrict__ b,
        float* __restrict__ O){
    __shared__ float sx[128*66];
    __shared__ float smu2[128], srs[128];
    int t = threadIdx.x;
    size_t base = (size_t)blockIdx.x * 128;
    for(int s=t;s<4096;s+=256){
        int p = s >> 5, j2 = s & 31;
        float2 v = *(const float2*)(X + (base+p)*64 + j2*2);
        sx[p*66 + j2*2]   = v.x;
        sx[p*66 + j2*2+1] = v.y;
    }
    __syncthreads();
    if(t<128){
        float mu=0.f, m2=0.f;
        const float* r = sx + t*66;
        #pragma unroll 8
        for(int j=0;j<64;j++){ float v=r[j]; mu+=v; m2+=v*v; }
        mu *= (1.f/64.f);
        float var = fmaxf(m2*(1.f/64.f) - mu*mu, 0.f);
        smu2[t]=mu; srs[t]=rsqrtf(var+1e-5f);
    }
    __syncthreads();
    for(int s=t;s<4096;s+=256){
        int p = s >> 5, j2 = s & 31;
        float mu=smu2[p], rs=srs[p];
        int j = j2*2;
        float2 v;
        v.x = (sx[p*66+j]  -mu)*rs*g[j]  +b[j];
        v.y = (sx[p*66+j+1]-mu)*rs*g[j+1]+b[j+1];
        *(float2*)(O + (base+p)*64 + j) = v;
    }
}

// ---------------- mask gate (float4) ---------------------------------------
__global__ __launch_bounds__(256) void k_maskgate(const float* __restrict__ T,
        const float* __restrict__ M1, const float* __restrict__ V,
        const float* __restrict__ dw, const float* __restrict__ db,
        float* __restrict__ VG){
    __shared__ float4 sdw[400];
    __shared__ float4 sdb4[16];
    int tid=threadIdx.x;
    for(int i=tid;i<400;i+=256) sdw[i]=((const float4*)dw)[i];
    if(tid<16) sdb4[tid]=((const float4*)db)[tid];
    __syncthreads();
    size_t e=(size_t)blockIdx.x*256+tid;
    int c4=(int)(e&15);
    size_t p=e>>4;
    int b=(int)(p>>16);
    int pp=(int)(p&65535);
    int y=pp>>8, x=pp&255;
    float4 conv=make_float4(0,0,0,0);
    #pragma unroll
    for(int dy=0;dy<5;dy++){
        int yy=y+dy-2; if(yy<0||yy>255) continue;
        #pragma unroll
        for(int dx=0;dx<5;dx++){
            int xx=x+dx-2; if(xx<0||xx>255) continue;
            float4 tv = *(const float4*)(T + (((((size_t)b<<16)+(yy<<8)+xx)<<6)+c4*4));
            float4 wv = sdw[(dy*5+dx)*16+c4];
            conv.x+=tv.x*wv.x; conv.y+=tv.y*wv.y; conv.z+=tv.z*wv.z; conv.w+=tv.w*wv.w;
        }
    }
    float4 bb=sdb4[c4];
    float4 m1=((const float4*)M1)[e];
    float4 vv=((const float4*)V)[e];
    float4 r;
    r.x = vv.x*m1.x*(1.f+1.f/(1.f+expf(-(conv.x+bb.x))));
    r.y = vv.y*m1.y*(1.f+1.f/(1.f+expf(-(conv.y+bb.y))));
    r.z = vv.z*m1.z*(1.f+1.f/(1.f+expf(-(conv.z+bb.z))));
    r.w = vv.w*m1.w*(1.f+1.f/(1.f+expf(-(conv.w+bb.w))));
    ((float4*)VG)[e]=r;
}

// ---------------- depthwise 3x3 + GELU (float4, C=1<<cbits) ----------------
__global__ __launch_bounds__(256) void k_dw3_gelu(const float* __restrict__ in,
        const float* __restrict__ dw, float* __restrict__ out, int cbits){
    __shared__ float4 sdw[576];
    int tid=threadIdx.x;
    int C4=1<<(cbits-2);
    for(int i=tid;i<9*C4;i+=256) sdw[i]=((const float4*)dw)[i];
    __syncthreads();
    size_t e=(size_t)blockIdx.x*256+tid;
    int c4=(int)(e&(C4-1));
    size_t p=e>>(cbits-2);
    int b=(int)(p>>16), pp=(int)(p&65535), y=pp>>8, x=pp&255;
    float4 conv=make_float4(0,0,0,0);
    #pragma unroll
    for(int dy=0;dy<3;dy++){
        int yy=y+dy-1; if(yy<0||yy>255) continue;
        #pragma unroll
        for(int dx=0;dx<3;dx++){
            int xx=x+dx-1; if(xx<0||xx>255) continue;
            float4 tv = *(const float4*)(in + ((((((size_t)b<<16)+(yy<<8)+xx))<<cbits)+c4*4));
            float4 wv = sdw[(dy*3+dx)*C4+c4];
            conv.x+=tv.x*wv.x; conv.y+=tv.y*wv.y; conv.z+=tv.z*wv.z; conv.w+=tv.w*wv.w;
        }
    }
    float4 r=make_float4(gelu_f(conv.x),gelu_f(conv.y),gelu_f(conv.z),gelu_f(conv.w));
    ((float4*)out)[e]=r;
}

// ---------------- msa epilogue: X += dw3(P, pe2) (float4) ------------------
__global__ __launch_bounds__(256) void k_msa_out(
        const float* __restrict__ P, const float* __restrict__ pe2,
        float* __restrict__ X){
    __shared__ float4 sdw[144];
    int tid=threadIdx.x;
    if(tid<144) sdw[tid]=((const float4*)pe2)[tid];
    __syncthreads();
    size_t e=(size_t)blockIdx.x*256+tid;
    int c4=(int)(e&15);
    size_t p=e>>4;
    int b=(int)(p>>16), pp=(int)(p&65535), y=pp>>8, x=pp&255;
    float4 conv=make_float4(0,0,0,0);
    #pragma unroll
    for(int dy=0;dy<3;dy++){
        int yy=y+dy-1; if(yy<0||yy>255) continue;
        #pragma unroll
        for(int dx=0;dx<3;dx++){
            int xx=x+dx-1; if(xx<0||xx>255) continue;
            float4 tv = *(const float4*)(P + (((((size_t)b<<16)+(yy<<8)+xx)<<6)+c4*4));
            float4 wv = sdw[(dy*3+dx)*16+c4];
            conv.x+=tv.x*wv.x; conv.y+=tv.y*wv.y; conv.z+=tv.z*wv.z; conv.w+=tv.w*wv.w;
        }
    }
    float4 xv=((float4*)X)[e];
    xv.x+=conv.x; xv.y+=conv.y; xv.z+=conv.z; xv.w+=conv.w;
    ((float4*)X)[e]=xv;
}

// ---------------- host -----------------------------------------------------
extern "C" void kernel_launch(void* const* d_in, const int* in_sizes, int n_in,
                              void* d_out, int out_size){
    const float* x    = (const float*)d_in[0];
    const float* mask = (const float*)d_in[1];
    const float* Wq   = (const float*)d_in[2];
    const float* Wk   = (const float*)d_in[3];
    const float* Wv   = (const float*)d_in[4];
    const float* resc = (const float*)d_in[5];
    const float* Wp   = (const float*)d_in[6];
    const float* bp   = (const float*)d_in[7];
    const float* pe1  = (const float*)d_in[8];
    const float* pe2  = (const float*)d_in[9];
    const float* mw1  = (const float*)d_in[10];
    const float* mb1  = (const float*)d_in[11];
    const float* mw2  = (const float*)d_in[12];
    const float* mb2  = (const float*)d_in[13];
    const float* mdw  = (const float*)d_in[14];
    const float* mdb  = (const float*)d_in[15];
    const float* lng  = (const float*)d_in[16];
    const float* lnb  = (const float*)d_in[17];
    const float* fw1  = (const float*)d_in[18];
    const float* fdw  = (const float*)d_in[19];
    const float* fw2  = (const float*)d_in[20];
    float* out = (float*)d_out;

    float *pX,*pM,*pQ,*pK,*pV,*pT1,*pH1,*pH2,*pGP,*pMC;
    cudaGetSymbolAddress((void**)&pX,  g_X);
    cudaGetSymbolAddress((void**)&pM,  g_Mk);
    cudaGetSymbolAddress((void**)&pQ,  g_Q);
    cudaGetSymbolAddress((void**)&pK,  g_K);
    cudaGetSymbolAddress((void**)&pV,  g_V);
    cudaGetSymbolAddress((void**)&pT1, g_T1);
    cudaGetSymbolAddress((void**)&pH1, g_H1);
    cudaGetSymbolAddress((void**)&pH2, g_H2);
    cudaGetSymbolAddress((void**)&pGP, g_GP);
    cudaGetSymbolAddress((void**)&pMC, g_MC);

    cudaFuncSetAttribute(k_tmma<1,1,0>, cudaFuncAttributeMaxDynamicSharedMemorySize, TM_SMEM);
    cudaFuncSetAttribute(k_tmma<1,1,2>, cudaFuncAttributeMaxDynamicSharedMemorySize, TM_SMEM);
    cudaFuncSetAttribute(k_tmma<1,4,1>, cudaFuncAttributeMaxDynamicSharedMemorySize, TM_SMEM);
    cudaFuncSetAttribute(k_tmma<4,1,2>, cudaFuncAttributeMaxDynamicSharedMemorySize, TM_SMEM);

    dim3 tg(2048,2,2);
    k_nchw2nhwc<<<tg,256>>>(x,    pX);
    k_nchw2nhwc<<<tg,256>>>(mask, pM);

    for(int i=0;i<3;i++){
        const float* Wq_i  = Wq  + i*4096;
        const float* Wk_i  = Wk  + i*4096;
        const float* Wv_i  = Wv  + i*4096;
        const float* Wp_i  = Wp  + i*4096;
        const float* mw1_i = mw1 + i*4096;
        const float* mw2_i = mw2 + i*4096;
        const float* bp_i  = bp  + i*64;
        const float* mb1_i = mb1 + i*64;
        const float* mb2_i = mb2 + i*64;
        const float* mdb_i = mdb + i*64;
        const float* lng_i = lng + i*64;
        const float* lnb_i = lnb + i*64;
        const float* pe1_i = pe1 + i*576;
        const float* pe2_i = pe2 + i*576;
        const float* mdw_i = mdw + i*1600;
        const float* rs_i  = resc+ i*4;
        const float* fw1_i = fw1 + i*64*256;
        const float* fdw_i = fdw + i*9*256;
        const float* fw2_i = fw2 + i*256*64;

        // attention stats path
        k_tmma<1,1,0><<<1024,128,TM_SMEM>>>(pX, 64, Wq_i, 64, 0, nullptr, pQ, 64);
        k_tmma<1,1,0><<<1024,128,TM_SMEM>>>(pX, 64, Wk_i, 64, 0, nullptr, pK, 64);
        k_gram<<<dim3(128,2),256>>>(pQ, pK, pGP);
        k_attn<<<1,256>>>(pGP, Wp_i, rs_i, pMC);
        // v + mask gate
        k_tmma<1,1,0><<<1024,128,TM_SMEM>>>(pX, 64, Wv_i, 64, 0, nullptr, pV, 64);
        k_tmma<1,1,0><<<1024,128,TM_SMEM>>>(pM, 64, mw1_i, 64, 0, mb1_i, pT1, 64);
        k_tmma<1,1,0><<<1024,128,TM_SMEM>>>(pT1, 64, mw2_i, 64, 0, mb2_i, pQ, 64);
        k_maskgate<<<8192,256>>>(pQ, pT1, pV, mdw_i, mdb_i, pT1);    // VG -> g_T1
        // positional path
        k_dw3_gelu<<<8192,256>>>(pV, pe1_i, pK, 6);                  // P -> g_K
        // folded attention apply + proj, added straight into X
        k_tmma<1,1,2><<<1024,128,TM_SMEM>>>(pT1, 64, pMC, 64, 4096, bp_i, pX, 64);
        k_msa_out<<<8192,256>>>(pK, pe2_i, pX);                      // X += dw3(P)
        // feed-forward
        k_ln<<<1024,256>>>(pX, lng_i, lnb_i, pT1);
        k_tmma<1,4,1><<<dim3(1024,1),128,TM_SMEM>>>(pT1, 64, fw1_i, 256, 0, nullptr, pH1, 256);
        k_dw3_gelu<<<32768,256>>>(pH1, fdw_i, pH2, 8);
        k_tmma<4,1,2><<<1024,128,TM_SMEM>>>(pH2, 256, fw2_i, 64, 0, nullptr, pX, 64);
    }

    k_nhwc2nchw<<<tg,256>>>(pX, out);
}

// round 14
// speedup vs baseline: 1.4884x; 1.4884x over previous
#include <cuda_runtime.h>
#include <math.h>
#include <stdint.h>

#define NPB 65536
#define NT  131072

// ---------------- scratch ----------
__device__ float g_X [NT*64];
__device__ float g_Mk[NT*64];
__device__ float g_Q [NT*64];
__device__ float g_K [NT*64];
__device__ float g_V [NT*64];
__device__ float g_T1[NT*64];
__device__ float g_H1[NT*256];
__device__ float g_H2[NT*256];
__device__ float g_GP[2*128*1152];
__device__ float g_MC[2*64*64];

__device__ __forceinline__ float gelu_f(float u){
    return 0.5f*u*(1.f+erff(u*0.70710678118654752f));
}
__device__ __forceinline__ uint32_t tf32c(float f){
    uint32_t r; asm("cvt.rna.tf32.f32 %0, %1;" : "=r"(r) : "f"(f)); return r;
}
#define MMA_TF32(d, a, b0, b1) \
  asm volatile("mma.sync.aligned.m16n8k8.row.col.f32.tf32.tf32.f32 " \
    "{%0,%1,%2,%3},{%4,%5,%6,%7},{%8,%9},{%0,%1,%2,%3};" \
    : "+f"((d)[0]),"+f"((d)[1]),"+f"((d)[2]),"+f"((d)[3]) \
    : "r"((a)[0]),"r"((a)[1]),"r"((a)[2]),"r"((a)[3]),"r"(b0),"r"(b1))

// ---------------- tf32 tensor GEMM, 256-thread / high-occupancy ------------
// Tile 128px(M) x 64out(N), K=64 per chunk. 256 threads = 8 warps.
// Warp w owns px rows [w*16, w*16+16) (one m16 tile); 8 n8 tiles; 8 k-steps.
#define XS_STRIDE 68
#define WS_STRIDE 72
#define XS_U (128*XS_STRIDE)
#define WS_U (64*WS_STRIDE)
#define TM_SMEM ((XS_U + WS_U + 64)*4)

template<int KC,int NC,int MODE>
__global__ __launch_bounds__(256, 3) void k_tmma(
        const float* __restrict__ X, int xStride,
        const float* __restrict__ W, int wStride, int wBatchStride,
        const float* __restrict__ bias,
        float* __restrict__ OUT, int oStride){
    extern __shared__ uint32_t smu[];
    uint32_t* xs = smu;
    uint32_t* ws = smu + XS_U;
    float*    sb = (float*)(smu + XS_U + WS_U);
    const int t = threadIdx.x;
    const int warp = t>>5, lane = t&31;
    const int lr = lane>>2, lc = lane&3;
    const int m0 = warp*16;
    const size_t tileBase = (size_t)blockIdx.x*128;
    const float* Wb = W + (wBatchStride ? (int)(tileBase>>16)*(size_t)wBatchStride : 0);
    if(bias && t<64) sb[t] = bias[t];

    float acc[32];
    const int CH = (KC>NC)?KC:NC;

    for(int c=0;c<CH;c++){
        const int kOff = (KC>1)? c*64 : 0;
        const int nOff = (NC>1)? c*64 : 0;
        if(c) __syncthreads();
        if(c==0 || KC>1){
            #pragma unroll
            for(int it=0;it<8;it++){
                int s4 = t + it*256;
                int p = s4>>4, c4 = s4&15;
                float4 v = *(const float4*)(X + (tileBase+p)*(size_t)xStride + kOff + c4*4);
                uint32_t* xr = xs + p*XS_STRIDE + c4*4;
                xr[0]=tf32c(v.x); xr[1]=tf32c(v.y); xr[2]=tf32c(v.z); xr[3]=tf32c(v.w);
            }
        }
        #pragma unroll
        for(int it=0;it<16;it++){
            int s = t + it*256;
            int o = s&63, j = s>>6;
            ws[j*WS_STRIDE+o] = tf32c(Wb[(size_t)(kOff+j)*wStride + nOff + o]);
        }
        __syncthreads();
        if(c==0 || NC>1){
            if(bias){
                #pragma unroll
                for(int j=0;j<8;j++){
                    float b0 = sb[j*8 + 2*lc], b1 = sb[j*8 + 2*lc + 1];
                    acc[j*4+0]=b0; acc[j*4+1]=b1;
                    acc[j*4+2]=b0; acc[j*4+3]=b1;
                }
            } else {
                #pragma unroll
                for(int q=0;q<32;q++) acc[q]=0.f;
            }
        }
        #pragma unroll
        for(int k0=0;k0<64;k0+=8){
            uint32_t a[4];
            const uint32_t* xbp = xs + (m0+lr)*XS_STRIDE + k0 + lc;
            a[0]=xbp[0]; a[1]=xbp[8*XS_STRIDE];
            a[2]=xbp[4]; a[3]=xbp[8*XS_STRIDE+4];
            #pragma unroll
            for(int j=0;j<8;j++){
                uint32_t b0 = ws[(k0+lc  )*WS_STRIDE + j*8 + lr];
                uint32_t b1 = ws[(k0+lc+4)*WS_STRIDE + j*8 + lr];
                MMA_TF32(acc + j*4, a, b0, b1);
            }
        }
        if(NC>1 || c==CH-1){
            #pragma unroll
            for(int j=0;j<8;j++){
                size_t row = tileBase + m0 + lr;
                int col = nOff + j*8 + 2*lc;
                float v0=acc[j*4], v1=acc[j*4+1];
                float v2=acc[j*4+2], v3=acc[j*4+3];
                if(MODE==1){ v0=gelu_f(v0); v1=gelu_f(v1); v2=gelu_f(v2); v3=gelu_f(v3); }
                float* p0 = OUT + row*(size_t)oStride + col;
                float* p8 = p0 + 8*(size_t)oStride;
                if(MODE==2){
                    float2 o0 = *(float2*)p0, o8 = *(float2*)p8;
                    v0+=o0.x; v1+=o0.y; v2+=o8.x; v3+=o8.y;
                }
                *(float2*)p0 = make_float2(v0,v1);
                *(float2*)p8 = make_float2(v2,v3);
            }
        }
    }
}

// ---------------- gram partials via mma tf32 (R12-validated) ---------------
#define GR_STRIDE 68
__global__ __launch_bounds__(256) void k_gram(const float* __restrict__ Q,
        const float* __restrict__ K, float* __restrict__ gpart){
    __shared__ float sq[64*GR_STRIDE], sk[64*GR_STRIDE];
    const int t=threadIdx.x, warp=t>>5, lane=t&31;
    const int lr=lane>>2, lc=lane&3;
    const int b=blockIdx.y;
    const int h = warp&3;
    const int nb = (warp&1)*32;
    float accS[8];
    #pragma unroll
    for(int i=0;i<8;i++) accS[i]=0.f;
    float nrm=0.f;

    for(int ch=0; ch<8; ch++){
        size_t base = ((size_t)b*NPB + (size_t)blockIdx.x*512 + ch*64)*64;
        __syncthreads();
        #pragma unroll
        for(int it=0; it<4; it++){
            int s4 = t + it*256;
            int p = s4>>4, c4 = s4&15;
            float4 v = *(const float4*)(Q + base + p*64 + c4*4);
            float* r = sq + p*GR_STRIDE + c4*4;
            r[0]=v.x; r[1]=v.y; r[2]=v.z; r[3]=v.w;
            float4 w = *(const float4*)(K + base + p*64 + c4*4);
            float* r2 = sk + p*GR_STRIDE + c4*4;
            r2[0]=w.x; r2[1]=w.y; r2[2]=w.z; r2[3]=w.w;
        }
        __syncthreads();
        if(warp<4){
            #pragma unroll
            for(int k0=0;k0<64;k0+=8){
                uint32_t a[4];
                a[0]=tf32c(sk[(k0+lc  )*GR_STRIDE + h*16+lr  ]);
                a[1]=tf32c(sk[(k0+lc  )*GR_STRIDE + h*16+lr+8]);
                a[2]=tf32c(sk[(k0+lc+4)*GR_STRIDE + h*16+lr  ]);
                a[3]=tf32c(sk[(k0+lc+4)*GR_STRIDE + h*16+lr+8]);
                #pragma unroll
                for(int nt=0;nt<2;nt++){
                    uint32_t b0=tf32c(sq[(k0+lc  )*GR_STRIDE + h*16+nt*8+lr]);
                    uint32_t b1=tf32c(sq[(k0+lc+4)*GR_STRIDE + h*16+nt*8+lr]);
                    MMA_TF32(accS+nt*4, a, b0, b1);
                }
            }
        } else {
            const float* s = (warp<6)? sq : sk;
            int c = nb + lane;
            #pragma unroll 8
            for(int p=0;p<64;p++){ float v=s[p*GR_STRIDE+c]; nrm += v*v; }
        }
    }
    float* gp = gpart + ((size_t)b*128 + blockIdx.x)*1152;
    if(warp<4){
        float* gs = gp + h*256;
        #pragma unroll
        for(int nt=0;nt<2;nt++){
            int e0 = nt*8 + 2*lc;
            gs[lr*16 + e0]       = accS[nt*4+0];
            gs[lr*16 + e0+1]     = accS[nt*4+1];
            gs[(lr+8)*16 + e0]   = accS[nt*4+2];
            gs[(lr+8)*16 + e0+1] = accS[nt*4+3];
        }
    } else {
        int off = (warp<6)? 1024 : 1088;
        gp[off + nb + lane] = nrm;
    }
}

// ---------------- attn softmax + fold into Mcomb ---------------------------
__global__ __launch_bounds__(256) void k_attn(const float* __restrict__ gpart,
        const float* __restrict__ Wp, const float* __restrict__ resc,
        float* __restrict__ Mcomb){
    __shared__ float sred[2304];
    __shared__ float sa[2048];
    int tid = threadIdx.x;
    for(int jj=tid;jj<2304;jj+=256){
        int b=jj/1152, j=jj-b*1152;
        float acc=0.f;
        for(int blk=0;blk<128;blk++) acc += gpart[((size_t)b*128+blk)*1152 + j];
        sred[jj]=acc;
    }
    __syncthreads();
    if(tid<128){
        int b=tid>>6, hd=tid&63, h=hd>>4, d=hd&15;
        float nk = fmaxf(sqrtf(sred[b*1152+1088+hd]),1e-6f);
        float r = resc[h];
        float row[16]; float mx=-1e30f;
        #pragma unroll
        for(int e=0;e<16;e++){
            float nq = fmaxf(sqrtf(sred[b*1152+1024+h*16+e]),1e-6f);
            float v = sred[b*1152 + h*256 + d*16 + e] / (nk*nq) * r;
            row[e]=v; mx=fmaxf(mx,v);
        }
        float s=0.f;
        #pragma unroll
        for(int e=0;e<16;e++){ row[e]=expf(row[e]-mx); s+=row[e]; }
        float inv=1.f/s;
        #pragma unroll
        for(int e=0;e<16;e++) sa[((b*4+h)*16+d)*16+e] = row[e]*inv;
    }
    __syncthreads();
    for(int job=tid;job<8192;job+=256){
        int b=job>>12, rem=job&4095, ci=rem>>6, co=rem&63;
        int h=ci>>4, e=ci&15;
        float acc=0.f;
        #pragma unroll
        for(int d=0;d<16;d++) acc += sa[((b*4+h)*16+d)*16+e] * Wp[(h*16+d)*64+co];
        Mcomb[job]=acc;
    }
}

// ---------------- transposes ----------------
__global__ __launch_bounds__(256) void k_nchw2nhwc(const float* __restrict__ in, float* __restrict__ out){
    __shared__ float t[32][33];
    int tx = threadIdx.x & 31, ty = threadIdx.x >> 5;
    int pt = blockIdx.x, ct = blockIdx.y, b = blockIdx.z;
    const float* ip = in  + (size_t)b*64*NPB;
    float*       op = out + (size_t)b*NPB*64;
    #pragma unroll
    for(int r=0;r<4;r++){
        int c = ct*32 + ty + r*8;
        t[ty+r*8][tx] = ip[(size_t)c*NPB + (size_t)pt*32 + tx];
    }
    __syncthreads();
    #pragma unroll
    for(int r=0;r<4;r++){
        int p = pt*32 + ty + r*8;
        op[(size_t)p*64 + ct*32 + tx] = t[tx][ty+r*8];
    }
}
__global__ __launch_bounds__(256) void k_nhwc2nchw(const float* __restrict__ in, float* __restrict__ out){
    __shared__ float t[32][33];
    int tx = threadIdx.x & 31, ty = threadIdx.x >> 5;
    int pt = blockIdx.x, ct = blockIdx.y, b = blockIdx.z;
    const float* ip = in  + (size_t)b*NPB*64;
    float*       op = out + (size_t)b*64*NPB;
    #pragma unroll
    for(int r=0;r<4;r++){
        int p = pt*32 + ty + r*8;
        t[ty+r*8][tx] = ip[(size_t)p*64 + ct*32 + tx];
    }
    __syncthreads();
    #pragma unroll
    for(int r=0;r<4;r++){
        int c = ct*32 + ty + r*8;
        op[(size_t)c*NPB + (size_t)pt*32 + tx] = t[tx][ty+r*8];
    }
}

// ---------------- coalesced LayerNorm --------------------------------------
__global__ __launch_bounds__(256) void k_ln(const float* __restrict__ X,
        const float* __restrict__ g, const float* __restrict__ b,
        float* __restrict__ O){
    __shared__ float sx[128*66];
    __shared__ float smu2[128], srs[128];
    int t = threadIdx.x;
    size_t base = (size_t)blockIdx.x * 128;
    for(int s=t;s<4096;s+=256){
        int p = s >> 5, j2 = s & 31;
        float2 v = *(const float2*)(X + (base+p)*64 + j2*2);
        sx[p*66 + j2*2]   = v.x;
        sx[p*66 + j2*2+1] = v.y;
    }
    __syncthreads();
    if(t<128){
        float mu=0.f, m2=0.f;
        const float* r = sx + t*66;
        #pragma unroll 8
        for(int j=0;j<64;j++){ float v=r[j]; mu+=v; m2+=v*v; }
        mu *= (1.f/64.f);
        float var = fmaxf(m2*(1.f/64.f) - mu*mu, 0.f);
        smu2[t]=mu; srs[t]=rsqrtf(var+1e-5f);
    }
    __syncthreads();
    for(int s=t;s<4096;s+=256){
        int p = s >> 5, j2 = s & 31;
        float mu=smu2[p], rs=srs[p];
        int j = j2*2;
        float2 v;
        v.x = (sx[p*66+j]  -mu)*rs*g[j]  +b[j];
        v.y = (sx[p*66+j+1]-mu)*rs*g[j+1]+b[j+1];
        *(float2*)(O + (base+p)*64 + j) = v;
    }
}

// ---------------- mask gate (float4) ---------------------------------------
__global__ __launch_bounds__(256) void k_maskgate(const float* __restrict__ T,
        const float* __restrict__ M1, const float* __restrict__ V,
        const float* __restrict__ dw, const float* __restrict__ db,
        float* __restrict__ VG){
    __shared__ float4 sdw[400];
    __shared__ float4 sdb4[16];
    int tid=threadIdx.x;
    for(int i=tid;i<400;i+=256) sdw[i]=((const float4*)dw)[i];
    if(tid<16) sdb4[tid]=((const float4*)db)[tid];
    __syncthreads();
    size_t e=(size_t)blockIdx.x*256+tid;
    int c4=(int)(e&15);
    size_t p=e>>4;
    int b=(int)(p>>16);
    int pp=(int)(p&65535);
    int y=pp>>8, x=pp&255;
    float4 conv=make_float4(0,0,0,0);
    #pragma unroll
    for(int dy=0;dy<5;dy++){
        int yy=y+dy-2; if(yy<0||yy>255) continue;
        #pragma unroll
        for(int dx=0;dx<5;dx++){
            int xx=x+dx-2; if(xx<0||xx>255) continue;
            float4 tv = *(const float4*)(T + (((((size_t)b<<16)+(yy<<8)+xx)<<6)+c4*4));
            float4 wv = sdw[(dy*5+dx)*16+c4];
            conv.x+=tv.x*wv.x; conv.y+=tv.y*wv.y; conv.z+=tv.z*wv.z; conv.w+=tv.w*wv.w;
        }
    }
    float4 bb=sdb4[c4];
    float4 m1=((const float4*)M1)[e];
    float4 vv=((const float4*)V)[e];
    float4 r;
    r.x = vv.x*m1.x*(1.f+1.f/(1.f+expf(-(conv.x+bb.x))));
    r.y = vv.y*m1.y*(1.f+1.f/(1.f+expf(-(conv.y+bb.y))));
    r.z = vv.z*m1.z*(1.f+1.f/(1.f+expf(-(conv.z+bb.z))));
    r.w = vv.w*m1.w*(1.f+1.f/(1.f+expf(-(conv.w+bb.w))));
    ((float4*)VG)[e]=r;
}

// ---------------- depthwise 3x3 + GELU (float4, C=1<<cbits) ----------------
__global__ __launch_bounds__(256) void k_dw3_gelu(const float* __restrict__ in,
        const float* __restrict__ dw, float* __restrict__ out, int cbits){
    __shared__ float4 sdw[576];
    int tid=threadIdx.x;
    int C4=1<<(cbits-2);
    for(int i=tid;i<9*C4;i+=256) sdw[i]=((const float4*)dw)[i];
    __syncthreads();
    size_t e=(size_t)blockIdx.x*256+tid;
    int c4=(int)(e&(C4-1));
    size_t p=e>>(cbits-2);
    int b=(int)(p>>16), pp=(int)(p&65535), y=pp>>8, x=pp&255;
    float4 conv=make_float4(0,0,0,0);
    #pragma unroll
    for(int dy=0;dy<3;dy++){
        int yy=y+dy-1; if(yy<0||yy>255) continue;
        #pragma unroll
        for(int dx=0;dx<3;dx++){
            int xx=x+dx-1; if(xx<0||xx>255) continue;
            float4 tv = *(const float4*)(in + ((((((size_t)b<<16)+(yy<<8)+xx))<<cbits)+c4*4));
            float4 wv = sdw[(dy*3+dx)*C4+c4];
            conv.x+=tv.x*wv.x; conv.y+=tv.y*wv.y; conv.z+=tv.z*wv.z; conv.w+=tv.w*wv.w;
        }
    }
    float4 r=make_float4(gelu_f(conv.x),gelu_f(conv.y),gelu_f(conv.z),gelu_f(conv.w));
    ((float4*)out)[e]=r;
}

// ---------------- msa epilogue: X += dw3(P, pe2) (float4) ------------------
__global__ __launch_bounds__(256) void k_msa_out(
        const float* __restrict__ P, const float* __restrict__ pe2,
        float* __restrict__ X){
    __shared__ float4 sdw[144];
    int tid=threadIdx.x;
    if(tid<144) sdw[tid]=((const float4*)pe2)[tid];
    __syncthreads();
    size_t e=(size_t)blockIdx.x*256+tid;
    int c4=(int)(e&15);
    size_t p=e>>4;
    int b=(int)(p>>16), pp=(int)(p&65535), y=pp>>8, x=pp&255;
    float4 conv=make_float4(0,0,0,0);
    #pragma unroll
    for(int dy=0;dy<3;dy++){
        int yy=y+dy-1; if(yy<0||yy>255) continue;
        #pragma unroll
        for(int dx=0;dx<3;dx++){
            int xx=x+dx-1; if(xx<0||xx>255) continue;
            float4 tv = *(const float4*)(P + (((((size_t)b<<16)+(yy<<8)+xx)<<6)+c4*4));
            float4 wv = sdw[(dy*3+dx)*16+c4];
            conv.x+=tv.x*wv.x; conv.y+=tv.y*wv.y; conv.z+=tv.z*wv.z; conv.w+=tv.w*wv.w;
        }
    }
    float4 xv=((float4*)X)[e];
    xv.x+=conv.x; xv.y+=conv.y; xv.z+=conv.z; xv.w+=conv.w;
    ((float4*)X)[e]=xv;
}

// ---------------- host -----------------------------------------------------
extern "C" void kernel_launch(void* const* d_in, const int* in_sizes, int n_in,
                              void* d_out, int out_size){
    const float* x    = (const float*)d_in[0];
    const float* mask = (const float*)d_in[1];
    const float* Wq   = (const float*)d_in[2];
    const float* Wk   = (const float*)d_in[3];
    const float* Wv   = (const float*)d_in[4];
    const float* resc = (const float*)d_in[5];
    const float* Wp   = (const float*)d_in[6];
    const float* bp   = (const float*)d_in[7];
    const float* pe1  = (const float*)d_in[8];
    const float* pe2  = (const float*)d_in[9];
    const float* mw1  = (const float*)d_in[10];
    const float* mb1  = (const float*)d_in[11];
    const float* mw2  = (const float*)d_in[12];
    const float* mb2  = (const float*)d_in[13];
    const float* mdw  = (const float*)d_in[14];
    const float* mdb  = (const float*)d_in[15];
    const float* lng  = (const float*)d_in[16];
    const float* lnb  = (const float*)d_in[17];
    const float* fw1  = (const float*)d_in[18];
    const float* fdw  = (const float*)d_in[19];
    const float* fw2  = (const float*)d_in[20];
    float* out = (float*)d_out;

    float *pX,*pM,*pQ,*pK,*pV,*pT1,*pH1,*pH2,*pGP,*pMC;
    cudaGetSymbolAddress((void**)&pX,  g_X);
    cudaGetSymbolAddress((void**)&pM,  g_Mk);
    cudaGetSymbolAddress((void**)&pQ,  g_Q);
    cudaGetSymbolAddress((void**)&pK,  g_K);
    cudaGetSymbolAddress((void**)&pV,  g_V);
    cudaGetSymbolAddress((void**)&pT1, g_T1);
    cudaGetSymbolAddress((void**)&pH1, g_H1);
    cudaGetSymbolAddress((void**)&pH2, g_H2);
    cudaGetSymbolAddress((void**)&pGP, g_GP);
    cudaGetSymbolAddress((void**)&pMC, g_MC);

    cudaFuncSetAttribute(k_tmma<1,1,0>, cudaFuncAttributeMaxDynamicSharedMemorySize, TM_SMEM);
    cudaFuncSetAttribute(k_tmma<1,1,2>, cudaFuncAttributeMaxDynamicSharedMemorySize, TM_SMEM);
    cudaFuncSetAttribute(k_tmma<1,4,1>, cudaFuncAttributeMaxDynamicSharedMemorySize, TM_SMEM);
    cudaFuncSetAttribute(k_tmma<4,1,2>, cudaFuncAttributeMaxDynamicSharedMemorySize, TM_SMEM);

    dim3 tg(2048,2,2);
    k_nchw2nhwc<<<tg,256>>>(x,    pX);
    k_nchw2nhwc<<<tg,256>>>(mask, pM);

    for(int i=0;i<3;i++){
        const float* Wq_i  = Wq  + i*4096;
        const float* Wk_i  = Wk  + i*4096;
        const float* Wv_i  = Wv  + i*4096;
        const float* Wp_i  = Wp  + i*4096;
        const float* mw1_i = mw1 + i*4096;
        const float* mw2_i = mw2 + i*4096;
        const float* bp_i  = bp  + i*64;
        const float* mb1_i = mb1 + i*64;
        const float* mb2_i = mb2 + i*64;
        const float* mdb_i = mdb + i*64;
        const float* lng_i = lng + i*64;
        const float* lnb_i = lnb + i*64;
        const float* pe1_i = pe1 + i*576;
        const float* pe2_i = pe2 + i*576;
        const float* mdw_i = mdw + i*1600;
        const float* rs_i  = resc+ i*4;
        const float* fw1_i = fw1 + i*64*256;
        const float* fdw_i = fdw + i*9*256;
        const float* fw2_i = fw2 + i*256*64;

        // attention stats path
        k_tmma<1,1,0><<<1024,256,TM_SMEM>>>(pX, 64, Wq_i, 64, 0, nullptr, pQ, 64);
        k_tmma<1,1,0><<<1024,256,TM_SMEM>>>(pX, 64, Wk_i, 64, 0, nullptr, pK, 64);
        k_gram<<<dim3(128,2),256>>>(pQ, pK, pGP);
        k_attn<<<1,256>>>(pGP, Wp_i, rs_i, pMC);
        // v + mask gate
        k_tmma<1,1,0><<<1024,256,TM_SMEM>>>(pX, 64, Wv_i, 64, 0, nullptr, pV, 64);
        k_tmma<1,1,0><<<1024,256,TM_SMEM>>>(pM, 64, mw1_i, 64, 0, mb1_i, pT1, 64);
        k_tmma<1,1,0><<<1024,256,TM_SMEM>>>(pT1, 64, mw2_i, 64, 0, mb2_i, pQ, 64);
        k_maskgate<<<8192,256>>>(pQ, pT1, pV, mdw_i, mdb_i, pT1);    // VG -> g_T1
        // positional path
        k_dw3_gelu<<<8192,256>>>(pV, pe1_i, pK, 6);                  // P -> g_K
        // folded attention apply + proj, added straight into X
        k_tmma<1,1,2><<<1024,256,TM_SMEM>>>(pT1, 64, pMC, 64, 4096, bp_i, pX, 64);
        k_msa_out<<<8192,256>>>(pK, pe2_i, pX);                      // X += dw3(P)
        // feed-forward
        k_ln<<<1024,256>>>(pX, lng_i, lnb_i, pT1);
        k_tmma<1,4,1><<<dim3(1024,1),256,TM_SMEM>>>(pT1, 64, fw1_i, 256, 0, nullptr, pH1, 256);
        k_dw3_gelu<<<32768,256>>>(pH1, fdw_i, pH2, 8);
        k_tmma<4,1,2><<<1024,256,TM_SMEM>>>(pH2, 256, fw2_i, 64, 0, nullptr, pX, 64);
    }

    k_nhwc2nchw<<<tg,256>>>(pX, out);
}

// round 15
// speedup vs baseline: 1.5973x; 1.0732x over previous
#include <cuda_runtime.h>
#include <cuda_bf16.h>
#include <math.h>
#include <stdint.h>

#define NPB 65536
#define NT  131072

// ---------------- scratch ----------
__device__ float g_X [NT*64];
__device__ float g_Mk[NT*64];
__device__ float g_Q [NT*64];
__device__ float g_K [NT*64];
__device__ float g_V [NT*64];
__device__ float g_T1[NT*64];
__device__ __nv_bfloat16 g_H1[NT*256];
__device__ __nv_bfloat16 g_H2[NT*256];
__device__ float g_GP[2*128*1152];
__device__ float g_MC[2*64*64];

__device__ __forceinline__ float gelu_f(float u){
    return 0.5f*u*(1.f+erff(u*0.70710678118654752f));
}
__device__ __forceinline__ uint32_t tf32c(float f){
    uint32_t r; asm("cvt.rna.tf32.f32 %0, %1;" : "=r"(r) : "f"(f)); return r;
}
#define MMA_TF32(d, a, b0, b1) \
  asm volatile("mma.sync.aligned.m16n8k8.row.col.f32.tf32.tf32.f32 " \
    "{%0,%1,%2,%3},{%4,%5,%6,%7},{%8,%9},{%0,%1,%2,%3};" \
    : "+f"((d)[0]),"+f"((d)[1]),"+f"((d)[2]),"+f"((d)[3]) \
    : "r"((a)[0]),"r"((a)[1]),"r"((a)[2]),"r"((a)[3]),"r"(b0),"r"(b1))

// ---------------- tf32 tensor GEMM, 256-thread ------------------------------
// Tile 128px(M) x 64out(N), K=64 per chunk. 256 threads = 8 warps.
// IOBF: 0 = fp32 in/out, 1 = bf16 OUT, 2 = bf16 X.
#define XS_STRIDE 68
#define WS_STRIDE 72
#define XS_U (128*XS_STRIDE)
#define WS_U (64*WS_STRIDE)
#define TM_SMEM ((XS_U + WS_U + 64)*4)

template<int KC,int NC,int MODE,int IOBF>
__global__ __launch_bounds__(256, 3) void k_tmma(
        const void* __restrict__ Xv, int xStride,
        const float* __restrict__ W, int wStride, int wBatchStride,
        const float* __restrict__ bias,
        void* __restrict__ OUTv, int oStride){
    extern __shared__ uint32_t smu[];
    uint32_t* xs = smu;
    uint32_t* ws = smu + XS_U;
    float*    sb = (float*)(smu + XS_U + WS_U);
    const int t = threadIdx.x;
    const int warp = t>>5, lane = t&31;
    const int lr = lane>>2, lc = lane&3;
    const int m0 = warp*16;
    const size_t tileBase = (size_t)blockIdx.x*128;
    const float* Wb = W + (wBatchStride ? (int)(tileBase>>16)*(size_t)wBatchStride : 0);
    if(bias && t<64) sb[t] = bias[t];

    float acc[32];
    const int CH = (KC>NC)?KC:NC;

    for(int c=0;c<CH;c++){
        const int kOff = (KC>1)? c*64 : 0;
        const int nOff = (NC>1)? c*64 : 0;
        if(c) __syncthreads();
        if(c==0 || KC>1){
            #pragma unroll
            for(int it=0;it<8;it++){
                int s4 = t + it*256;
                int p = s4>>4, c4 = s4&15;
                float vx,vy,vz,vw;
                if(IOBF==2){
                    const __nv_bfloat16* Xb = (const __nv_bfloat16*)Xv;
                    uint2 raw = *(const uint2*)(Xb + (tileBase+p)*(size_t)xStride + kOff + c4*4);
                    __nv_bfloat162 b01 = *reinterpret_cast<__nv_bfloat162*>(&raw.x);
                    __nv_bfloat162 b23 = *reinterpret_cast<__nv_bfloat162*>(&raw.y);
                    float2 f01 = __bfloat1622float2(b01);
                    float2 f23 = __bfloat1622float2(b23);
                    vx=f01.x; vy=f01.y; vz=f23.x; vw=f23.y;
                } else {
                    const float* Xf = (const float*)Xv;
                    float4 v = *(const float4*)(Xf + (tileBase+p)*(size_t)xStride + kOff + c4*4);
                    vx=v.x; vy=v.y; vz=v.z; vw=v.w;
                }
                uint32_t* xr = xs + p*XS_STRIDE + c4*4;
                xr[0]=tf32c(vx); xr[1]=tf32c(vy); xr[2]=tf32c(vz); xr[3]=tf32c(vw);
            }
        }
        #pragma unroll
        for(int it=0;it<16;it++){
            int s = t + it*256;
            int o = s&63, j = s>>6;
            ws[j*WS_STRIDE+o] = tf32c(Wb[(size_t)(kOff+j)*wStride + nOff + o]);
        }
        __syncthreads();
        if(c==0 || NC>1){
            if(bias){
                #pragma unroll
                for(int j=0;j<8;j++){
                    float b0 = sb[j*8 + 2*lc], b1 = sb[j*8 + 2*lc + 1];
                    acc[j*4+0]=b0; acc[j*4+1]=b1;
                    acc[j*4+2]=b0; acc[j*4+3]=b1;
                }
            } else {
                #pragma unroll
                for(int q=0;q<32;q++) acc[q]=0.f;
            }
        }
        #pragma unroll
        for(int k0=0;k0<64;k0+=8){
            uint32_t a[4];
            const uint32_t* xbp = xs + (m0+lr)*XS_STRIDE + k0 + lc;
            a[0]=xbp[0]; a[1]=xbp[8*XS_STRIDE];
            a[2]=xbp[4]; a[3]=xbp[8*XS_STRIDE+4];
            #pragma unroll
            for(int j=0;j<8;j++){
                uint32_t b0 = ws[(k0+lc  )*WS_STRIDE + j*8 + lr];
                uint32_t b1 = ws[(k0+lc+4)*WS_STRIDE + j*8 + lr];
                MMA_TF32(acc + j*4, a, b0, b1);
            }
        }
        if(NC>1 || c==CH-1){
            #pragma unroll
            for(int j=0;j<8;j++){
                size_t row = tileBase + m0 + lr;
                int col = nOff + j*8 + 2*lc;
                float v0=acc[j*4], v1=acc[j*4+1];
                float v2=acc[j*4+2], v3=acc[j*4+3];
                if(MODE==1){ v0=gelu_f(v0); v1=gelu_f(v1); v2=gelu_f(v2); v3=gelu_f(v3); }
                if(IOBF==1){
                    __nv_bfloat16* Ob = (__nv_bfloat16*)OUTv;
                    __nv_bfloat16* p0 = Ob + row*(size_t)oStride + col;
                    __nv_bfloat16* p8 = p0 + 8*(size_t)oStride;
                    *(__nv_bfloat162*)p0 = __float22bfloat162_rn(make_float2(v0,v1));
                    *(__nv_bfloat162*)p8 = __float22bfloat162_rn(make_float2(v2,v3));
                } else {
                    float* Of = (float*)OUTv;
                    float* p0 = Of + row*(size_t)oStride + col;
                    float* p8 = p0 + 8*(size_t)oStride;
                    if(MODE==2){
                        float2 o0 = *(float2*)p0, o8 = *(float2*)p8;
                        v0+=o0.x; v1+=o0.y; v2+=o8.x; v3+=o8.y;
                    }
                    *(float2*)p0 = make_float2(v0,v1);
                    *(float2*)p8 = make_float2(v2,v3);
                }
            }
        }
    }
}

// ---------------- gram partials via mma tf32 --------------------------------
#define GR_STRIDE 68
__global__ __launch_bounds__(256) void k_gram(const float* __restrict__ Q,
        const float* __restrict__ K, float* __restrict__ gpart){
    __shared__ float sq[64*GR_STRIDE], sk[64*GR_STRIDE];
    const int t=threadIdx.x, warp=t>>5, lane=t&31;
    const int lr=lane>>2, lc=lane&3;
    const int b=blockIdx.y;
    const int h = warp&3;
    const int nb = (warp&1)*32;
    float accS[8];
    #pragma unroll
    for(int i=0;i<8;i++) accS[i]=0.f;
    float nrm=0.f;

    for(int ch=0; ch<8; ch++){
        size_t base = ((size_t)b*NPB + (size_t)blockIdx.x*512 + ch*64)*64;
        __syncthreads();
        #pragma unroll
        for(int it=0; it<4; it++){
            int s4 = t + it*256;
            int p = s4>>4, c4 = s4&15;
            float4 v = *(const float4*)(Q + base + p*64 + c4*4);
            float* r = sq + p*GR_STRIDE + c4*4;
            r[0]=v.x; r[1]=v.y; r[2]=v.z; r[3]=v.w;
            float4 w = *(const float4*)(K + base + p*64 + c4*4);
            float* r2 = sk + p*GR_STRIDE + c4*4;
            r2[0]=w.x; r2[1]=w.y; r2[2]=w.z; r2[3]=w.w;
        }
        __syncthreads();
        if(warp<4){
            #pragma unroll
            for(int k0=0;k0<64;k0+=8){
                uint32_t a[4];
                a[0]=tf32c(sk[(k0+lc  )*GR_STRIDE + h*16+lr  ]);
                a[1]=tf32c(sk[(k0+lc  )*GR_STRIDE + h*16+lr+8]);
                a[2]=tf32c(sk[(k0+lc+4)*GR_STRIDE + h*16+lr  ]);
                a[3]=tf32c(sk[(k0+lc+4)*GR_STRIDE + h*16+lr+8]);
                #pragma unroll
                for(int nt=0;nt<2;nt++){
                    uint32_t b0=tf32c(sq[(k0+lc  )*GR_STRIDE + h*16+nt*8+lr]);
                    uint32_t b1=tf32c(sq[(k0+lc+4)*GR_STRIDE + h*16+nt*8+lr]);
                    MMA_TF32(accS+nt*4, a, b0, b1);
                }
            }
        } else {
            const float* s = (warp<6)? sq : sk;
            int c = nb + lane;
            #pragma unroll 8
            for(int p=0;p<64;p++){ float v=s[p*GR_STRIDE+c]; nrm += v*v; }
        }
    }
    float* gp = gpart + ((size_t)b*128 + blockIdx.x)*1152;
    if(warp<4){
        float* gs = gp + h*256;
        #pragma unroll
        for(int nt=0;nt<2;nt++){
            int e0 = nt*8 + 2*lc;
            gs[lr*16 + e0]       = accS[nt*4+0];
            gs[lr*16 + e0+1]     = accS[nt*4+1];
            gs[(lr+8)*16 + e0]   = accS[nt*4+2];
            gs[(lr+8)*16 + e0+1] = accS[nt*4+3];
        }
    } else {
        int off = (warp<6)? 1024 : 1088;
        gp[off + nb + lane] = nrm;
    }
}

// ---------------- attn softmax + fold into Mcomb ---------------------------
__global__ __launch_bounds__(256) void k_attn(const float* __restrict__ gpart,
        const float* __restrict__ Wp, const float* __restrict__ resc,
        float* __restrict__ Mcomb){
    __shared__ float sred[2304];
    __shared__ float sa[2048];
    int tid = threadIdx.x;
    for(int jj=tid;jj<2304;jj+=256){
        int b=jj/1152, j=jj-b*1152;
        float acc=0.f;
        for(int blk=0;blk<128;blk++) acc += gpart[((size_t)b*128+blk)*1152 + j];
        sred[jj]=acc;
    }
    __syncthreads();
    if(tid<128){
        int b=tid>>6, hd=tid&63, h=hd>>4, d=hd&15;
        float nk = fmaxf(sqrtf(sred[b*1152+1088+hd]),1e-6f);
        float r = resc[h];
        float row[16]; float mx=-1e30f;
        #pragma unroll
        for(int e=0;e<16;e++){
            float nq = fmaxf(sqrtf(sred[b*1152+1024+h*16+e]),1e-6f);
            float v = sred[b*1152 + h*256 + d*16 + e] / (nk*nq) * r;
            row[e]=v; mx=fmaxf(mx,v);
        }
        float s=0.f;
        #pragma unroll
        for(int e=0;e<16;e++){ row[e]=expf(row[e]-mx); s+=row[e]; }
        float inv=1.f/s;
        #pragma unroll
        for(int e=0;e<16;e++) sa[((b*4+h)*16+d)*16+e] = row[e]*inv;
    }
    __syncthreads();
    for(int job=tid;job<8192;job+=256){
        int b=job>>12, rem=job&4095, ci=rem>>6, co=rem&63;
        int h=ci>>4, e=ci&15;
        float acc=0.f;
        #pragma unroll
        for(int d=0;d<16;d++) acc += sa[((b*4+h)*16+d)*16+e] * Wp[(h*16+d)*64+co];
        Mcomb[job]=acc;
    }
}

// ---------------- transposes ----------------
__global__ __launch_bounds__(256) void k_nchw2nhwc(const float* __restrict__ in, float* __restrict__ out){
    __shared__ float t[32][33];
    int tx = threadIdx.x & 31, ty = threadIdx.x >> 5;
    int pt = blockIdx.x, ct = blockIdx.y, b = blockIdx.z;
    const float* ip = in  + (size_t)b*64*NPB;
    float*       op = out + (size_t)b*NPB*64;
    #pragma unroll
    for(int r=0;r<4;r++){
        int c = ct*32 + ty + r*8;
        t[ty+r*8][tx] = ip[(size_t)c*NPB + (size_t)pt*32 + tx];
    }
    __syncthreads();
    #pragma unroll
    for(int r=0;r<4;r++){
        int p = pt*32 + ty + r*8;
        op[(size_t)p*64 + ct*32 + tx] = t[tx][ty+r*8];
    }
}
__global__ __launch_bounds__(256) void k_nhwc2nchw(const float* __restrict__ in, float* __restrict__ out){
    __shared__ float t[32][33];
    int tx = threadIdx.x & 31, ty = threadIdx.x >> 5;
    int pt = blockIdx.x, ct = blockIdx.y, b = blockIdx.z;
    const float* ip = in  + (size_t)b*NPB*64;
    float*       op = out + (size_t)b*64*NPB;
    #pragma unroll
    for(int r=0;r<4;r++){
        int p = pt*32 + ty + r*8;
        t[ty+r*8][tx] = ip[(size_t)p*64 + ct*32 + tx];
    }
    __syncthreads();
    #pragma unroll
    for(int r=0;r<4;r++){
        int c = ct*32 + ty + r*8;
        op[(size_t)c*NPB + (size_t)pt*32 + tx] = t[tx][ty+r*8];
    }
}

// ---------------- coalesced LayerNorm --------------------------------------
__global__ __launch_bounds__(256) void k_ln(const float* __restrict__ X,
        const float* __restrict__ g, const float* __restrict__ b,
        float* __restrict__ O){
    __shared__ float sx[128*66];
    __shared__ float smu2[128], srs[128];
    int t = threadIdx.x;
    size_t base = (size_t)blockIdx.x * 128;
    for(int s=t;s<4096;s+=256){
        int p = s >> 5, j2 = s & 31;
        float2 v = *(const float2*)(X + (base+p)*64 + j2*2);
        sx[p*66 + j2*2]   = v.x;
        sx[p*66 + j2*2+1] = v.y;
    }
    __syncthreads();
    if(t<128){
        float mu=0.f, m2=0.f;
        const float* r = sx + t*66;
        #pragma unroll 8
        for(int j=0;j<64;j++){ float v=r[j]; mu+=v; m2+=v*v; }
        mu *= (1.f/64.f);
        float var = fmaxf(m2*(1.f/64.f) - mu*mu, 0.f);
        smu2[t]=mu; srs[t]=rsqrtf(var+1e-5f);
    }
    __syncthreads();
    for(int s=t;s<4096;s+=256){
        int p = s >> 5, j2 = s & 31;
        float mu=smu2[p], rs=srs[p];
        int j = j2*2;
        float2 v;
        v.x = (sx[p*66+j]  -mu)*rs*g[j]  +b[j];
        v.y = (sx[p*66+j+1]-mu)*rs*g[j+1]+b[j+1];
        *(float2*)(O + (base+p)*64 + j) = v;
    }
}

// ---------------- mask gate (float4) ---------------------------------------
__global__ __launch_bounds__(256) void k_maskgate(const float* __restrict__ T,
        const float* __restrict__ M1, const float* __restrict__ V,
        const float* __restrict__ dw, const float* __restrict__ db,
        float* __restrict__ VG){
    __shared__ float4 sdw[400];
    __shared__ float4 sdb4[16];
    int tid=threadIdx.x;
    for(int i=tid;i<400;i+=256) sdw[i]=((const float4*)dw)[i];
    if(tid<16) sdb4[tid]=((const float4*)db)[tid];
    __syncthreads();
    size_t e=(size_t)blockIdx.x*256+tid;
    int c4=(int)(e&15);
    size_t p=e>>4;
    int b=(int)(p>>16);
    int pp=(int)(p&65535);
    int y=pp>>8, x=pp&255;
    float4 conv=make_float4(0,0,0,0);
    #pragma unroll
    for(int dy=0;dy<5;dy++){
        int yy=y+dy-2; if(yy<0||yy>255) continue;
        #pragma unroll
        for(int dx=0;dx<5;dx++){
            int xx=x+dx-2; if(xx<0||xx>255) continue;
            float4 tv = *(const float4*)(T + (((((size_t)b<<16)+(yy<<8)+xx)<<6)+c4*4));
            float4 wv = sdw[(dy*5+dx)*16+c4];
            conv.x+=tv.x*wv.x; conv.y+=tv.y*wv.y; conv.z+=tv.z*wv.z; conv.w+=tv.w*wv.w;
        }
    }
    float4 bb=sdb4[c4];
    float4 m1=((const float4*)M1)[e];
    float4 vv=((const float4*)V)[e];
    float4 r;
    r.x = vv.x*m1.x*(1.f+1.f/(1.f+expf(-(conv.x+bb.x))));
    r.y = vv.y*m1.y*(1.f+1.f/(1.f+expf(-(conv.y+bb.y))));
    r.z = vv.z*m1.z*(1.f+1.f/(1.f+expf(-(conv.z+bb.z))));
    r.w = vv.w*m1.w*(1.f+1.f/(1.f+expf(-(conv.w+bb.w))));
    ((float4*)VG)[e]=r;
}

// ---------------- depthwise 3x3 + GELU fp32 (64ch) --------------------------
__global__ __launch_bounds__(256) void k_dw3_gelu(const float* __restrict__ in,
        const float* __restrict__ dw, float* __restrict__ out){
    __shared__ float4 sdw[144];
    int tid=threadIdx.x;
    if(tid<144) sdw[tid]=((const float4*)dw)[tid];
    __syncthreads();
    size_t e=(size_t)blockIdx.x*256+tid;
    int c4=(int)(e&15);
    size_t p=e>>4;
    int b=(int)(p>>16), pp=(int)(p&65535), y=pp>>8, x=pp&255;
    float4 conv=make_float4(0,0,0,0);
    #pragma unroll
    for(int dy=0;dy<3;dy++){
        int yy=y+dy-1; if(yy<0||yy>255) continue;
        #pragma unroll
        for(int dx=0;dx<3;dx++){
            int xx=x+dx-1; if(xx<0||xx>255) continue;
            float4 tv = *(const float4*)(in + (((((size_t)b<<16)+(yy<<8)+xx)<<6)+c4*4));
            float4 wv = sdw[(dy*3+dx)*16+c4];
            conv.x+=tv.x*wv.x; conv.y+=tv.y*wv.y; conv.z+=tv.z*wv.z; conv.w+=tv.w*wv.w;
        }
    }
    float4 r=make_float4(gelu_f(conv.x),gelu_f(conv.y),gelu_f(conv.z),gelu_f(conv.w));
    ((float4*)out)[e]=r;
}

// ---------------- depthwise 3x3 + GELU bf16 (256ch) -------------------------
__global__ __launch_bounds__(256) void k_dw3_gelu_bf(const __nv_bfloat16* __restrict__ in,
        const float* __restrict__ dw, __nv_bfloat16* __restrict__ out){
    __shared__ float4 sdw[576];
    int tid=threadIdx.x;
    for(int i=tid;i<576;i+=256) sdw[i]=((const float4*)dw)[i];
    __syncthreads();
    size_t e=(size_t)blockIdx.x*256+tid;
    int c4=(int)(e&63);
    size_t p=e>>6;
    int b=(int)(p>>16), pp=(int)(p&65535), y=pp>>8, x=pp&255;
    float4 conv=make_float4(0,0,0,0);
    #pragma unroll
    for(int dy=0;dy<3;dy++){
        int yy=y+dy-1; if(yy<0||yy>255) continue;
        #pragma unroll
        for(int dx=0;dx<3;dx++){
            int xx=x+dx-1; if(xx<0||xx>255) continue;
            uint2 raw = *(const uint2*)(in + (((((size_t)b<<16)+(yy<<8)+xx)<<8)+c4*4));
            __nv_bfloat162 b01 = *reinterpret_cast<__nv_bfloat162*>(&raw.x);
            __nv_bfloat162 b23 = *reinterpret_cast<__nv_bfloat162*>(&raw.y);
            float2 f01 = __bfloat1622float2(b01);
            float2 f23 = __bfloat1622float2(b23);
            float4 wv = sdw[(dy*3+dx)*64+c4];
            conv.x+=f01.x*wv.x; conv.y+=f01.y*wv.y; conv.z+=f23.x*wv.z; conv.w+=f23.y*wv.w;
        }
    }
    __nv_bfloat162 o01 = __float22bfloat162_rn(make_float2(gelu_f(conv.x),gelu_f(conv.y)));
    __nv_bfloat162 o23 = __float22bfloat162_rn(make_float2(gelu_f(conv.z),gelu_f(conv.w)));
    uint2 outr;
    outr.x = *reinterpret_cast<uint32_t*>(&o01);
    outr.y = *reinterpret_cast<uint32_t*>(&o23);
    *(uint2*)(out + e*4) = outr;
}

// ---------------- msa epilogue: X += dw3(P, pe2) (float4) ------------------
__global__ __launch_bounds__(256) void k_msa_out(
        const float* __restrict__ P, const float* __restrict__ pe2,
        float* __restrict__ X){
    __shared__ float4 sdw[144];
    int tid=threadIdx.x;
    if(tid<144) sdw[tid]=((const float4*)pe2)[tid];
    __syncthreads();
    size_t e=(size_t)blockIdx.x*256+tid;
    int c4=(int)(e&15);
    size_t p=e>>4;
    int b=(int)(p>>16), pp=(int)(p&65535), y=pp>>8, x=pp&255;
    float4 conv=make_float4(0,0,0,0);
    #pragma unroll
    for(int dy=0;dy<3;dy++){
        int yy=y+dy-1; if(yy<0||yy>255) continue;
        #pragma unroll
        for(int dx=0;dx<3;dx++){
            int xx=x+dx-1; if(xx<0||xx>255) continue;
            float4 tv = *(const float4*)(P + (((((size_t)b<<16)+(yy<<8)+xx)<<6)+c4*4));
            float4 wv = sdw[(dy*3+dx)*16+c4];
            conv.x+=tv.x*wv.x; conv.y+=tv.y*wv.y; conv.z+=tv.z*wv.z; conv.w+=tv.w*wv.w;
        }
    }
    float4 xv=((float4*)X)[e];
    xv.x+=conv.x; xv.y+=conv.y; xv.z+=conv.z; xv.w+=conv.w;
    ((float4*)X)[e]=xv;
}

// ---------------- host -----------------------------------------------------
extern "C" void kernel_launch(void* const* d_in, const int* in_sizes, int n_in,
                              void* d_out, int out_size){
    const float* x    = (const float*)d_in[0];
    const float* mask = (const float*)d_in[1];
    const float* Wq   = (const float*)d_in[2];
    const float* Wk   = (const float*)d_in[3];
    const float* Wv   = (const float*)d_in[4];
    const float* resc = (const float*)d_in[5];
    const float* Wp   = (const float*)d_in[6];
    const float* bp   = (const float*)d_in[7];
    const float* pe1  = (const float*)d_in[8];
    const float* pe2  = (const float*)d_in[9];
    const float* mw1  = (const float*)d_in[10];
    const float* mb1  = (const float*)d_in[11];
    const float* mw2  = (const float*)d_in[12];
    const float* mb2  = (const float*)d_in[13];
    const float* mdw  = (const float*)d_in[14];
    const float* mdb  = (const float*)d_in[15];
    const float* lng  = (const float*)d_in[16];
    const float* lnb  = (const float*)d_in[17];
    const float* fw1  = (const float*)d_in[18];
    const float* fdw  = (const float*)d_in[19];
    const float* fw2  = (const float*)d_in[20];
    float* out = (float*)d_out;

    float *pX,*pM,*pQ,*pK,*pV,*pT1,*pGP,*pMC;
    __nv_bfloat16 *pH1,*pH2;
    cudaGetSymbolAddress((void**)&pX,  g_X);
    cudaGetSymbolAddress((void**)&pM,  g_Mk);
    cudaGetSymbolAddress((void**)&pQ,  g_Q);
    cudaGetSymbolAddress((void**)&pK,  g_K);
    cudaGetSymbolAddress((void**)&pV,  g_V);
    cudaGetSymbolAddress((void**)&pT1, g_T1);
    cudaGetSymbolAddress((void**)&pH1, g_H1);
    cudaGetSymbolAddress((void**)&pH2, g_H2);
    cudaGetSymbolAddress((void**)&pGP, g_GP);
    cudaGetSymbolAddress((void**)&pMC, g_MC);

    cudaFuncSetAttribute(k_tmma<1,1,0,0>, cudaFuncAttributeMaxDynamicSharedMemorySize, TM_SMEM);
    cudaFuncSetAttribute(k_tmma<1,1,2,0>, cudaFuncAttributeMaxDynamicSharedMemorySize, TM_SMEM);
    cudaFuncSetAttribute(k_tmma<1,4,1,1>, cudaFuncAttributeMaxDynamicSharedMemorySize, TM_SMEM);
    cudaFuncSetAttribute(k_tmma<4,1,2,2>, cudaFuncAttributeMaxDynamicSharedMemorySize, TM_SMEM);

    dim3 tg(2048,2,2);
    k_nchw2nhwc<<<tg,256>>>(x,    pX);
    k_nchw2nhwc<<<tg,256>>>(mask, pM);

    for(int i=0;i<3;i++){
        const float* Wq_i  = Wq  + i*4096;
        const float* Wk_i  = Wk  + i*4096;
        const float* Wv_i  = Wv  + i*4096;
        const float* Wp_i  = Wp  + i*4096;
        const float* mw1_i = mw1 + i*4096;
        const float* mw2_i = mw2 + i*4096;
        const float* bp_i  = bp  + i*64;
        const float* mb1_i = mb1 + i*64;
        const float* mb2_i = mb2 + i*64;
        const float* mdb_i = mdb + i*64;
        const float* lng_i = lng + i*64;
        const float* lnb_i = lnb + i*64;
        const float* pe1_i = pe1 + i*576;
        const float* pe2_i = pe2 + i*576;
        const float* mdw_i = mdw + i*1600;
        const float* rs_i  = resc+ i*4;
        const float* fw1_i = fw1 + i*64*256;
        const float* fdw_i = fdw + i*9*256;
        const float* fw2_i = fw2 + i*256*64;

        // attention stats path
        k_tmma<1,1,0,0><<<1024,256,TM_SMEM>>>(pX, 64, Wq_i, 64, 0, nullptr, pQ, 64);
        k_tmma<1,1,0,0><<<1024,256,TM_SMEM>>>(pX, 64, Wk_i, 64, 0, nullptr, pK, 64);
        k_gram<<<dim3(128,2),256>>>(pQ, pK, pGP);
        k_attn<<<1,256>>>(pGP, Wp_i, rs_i, pMC);
        // v + mask gate
        k_tmma<1,1,0,0><<<1024,256,TM_SMEM>>>(pX, 64, Wv_i, 64, 0, nullptr, pV, 64);
        k_tmma<1,1,0,0><<<1024,256,TM_SMEM>>>(pM, 64, mw1_i, 64, 0, mb1_i, pT1, 64);
        k_tmma<1,1,0,0><<<1024,256,TM_SMEM>>>(pT1, 64, mw2_i, 64, 0, mb2_i, pQ, 64);
        k_maskgate<<<8192,256>>>(pQ, pT1, pV, mdw_i, mdb_i, pT1);    // VG -> g_T1
        // positional path
        k_dw3_gelu<<<8192,256>>>(pV, pe1_i, pK);                     // P -> g_K
        // folded attention apply + proj, added straight into X
        k_tmma<1,1,2,0><<<1024,256,TM_SMEM>>>(pT1, 64, pMC, 64, 4096, bp_i, pX, 64);
        k_msa_out<<<8192,256>>>(pK, pe2_i, pX);                      // X += dw3(P)
        // feed-forward (bf16 intermediates)
        k_ln<<<1024,256>>>(pX, lng_i, lnb_i, pT1);
        k_tmma<1,4,1,1><<<1024,256,TM_SMEM>>>(pT1, 64, fw1_i, 256, 0, nullptr, pH1, 256);
        k_dw3_gelu_bf<<<32768,256>>>(pH1, fdw_i, pH2);
        k_tmma<4,1,2,2><<<1024,256,TM_SMEM>>>(pH2, 256, fw2_i, 64, 0, nullptr, pX, 64);
    }

    k_nhwc2nchw<<<tg,256>>>(pX, out);
}

// round 16
// speedup vs baseline: 1.6200x; 1.0142x over previous
#include <cuda_runtime.h>
#include <cuda_bf16.h>
#include <math.h>
#include <stdint.h>

#define NPB 65536
#define NT  131072
typedef __nv_bfloat16 bf16;
typedef __nv_bfloat162 bf162;

// ---------------- scratch ----------
__device__ float g_X [NT*64];
__device__ float g_Mk[NT*64];
__device__ bf16  g_Q [NT*64];
__device__ bf16  g_K [NT*64];
__device__ bf16  g_V [NT*64];
__device__ bf16  g_T1[NT*64];
__device__ bf16  g_H1[NT*256];
__device__ bf16  g_H2[NT*256];
__device__ float g_GP[2*128*1152];
__device__ float g_MC[2*64*64];

__device__ __forceinline__ float gelu_f(float u){
    return 0.5f*u*(1.f+erff(u*0.70710678118654752f));
}
__device__ __forceinline__ uint32_t tf32c(float f){
    uint32_t r; asm("cvt.rna.tf32.f32 %0, %1;" : "=r"(r) : "f"(f)); return r;
}
__device__ __forceinline__ void ld_bf4(const bf16* p, float&a, float&b, float&c, float&d){
    uint2 raw = *(const uint2*)p;
    float2 f01 = __bfloat1622float2(*reinterpret_cast<bf162*>(&raw.x));
    float2 f23 = __bfloat1622float2(*reinterpret_cast<bf162*>(&raw.y));
    a=f01.x; b=f01.y; c=f23.x; d=f23.y;
}
__device__ __forceinline__ void st_bf4(bf16* p, float a, float b, float c, float d){
    uint2 r;
    bf162 o01 = __float22bfloat162_rn(make_float2(a,b));
    bf162 o23 = __float22bfloat162_rn(make_float2(c,d));
    r.x = *reinterpret_cast<uint32_t*>(&o01);
    r.y = *reinterpret_cast<uint32_t*>(&o23);
    *(uint2*)p = r;
}
#define MMA_TF32(d, a, b0, b1) \
  asm volatile("mma.sync.aligned.m16n8k8.row.col.f32.tf32.tf32.f32 " \
    "{%0,%1,%2,%3},{%4,%5,%6,%7},{%8,%9},{%0,%1,%2,%3};" \
    : "+f"((d)[0]),"+f"((d)[1]),"+f"((d)[2]),"+f"((d)[3]) \
    : "r"((a)[0]),"r"((a)[1]),"r"((a)[2]),"r"((a)[3]),"r"(b0),"r"(b1))

// ---------------- tf32 tensor GEMM, 256-thread ------------------------------
// Tile 128px(M) x 64out(N), K=64/chunk. INBF/OUTBF: bf16 input / output.
#define XS_STRIDE 68
#define WS_STRIDE 72
#define XS_U (128*XS_STRIDE)
#define WS_U (64*WS_STRIDE)
#define TM_SMEM ((XS_U + WS_U + 64)*4)

template<int KC,int NC,int MODE,int INBF,int OUTBF>
__global__ __launch_bounds__(256, 3) void k_tmma(
        const void* __restrict__ Xv, int xStride,
        const float* __restrict__ W, int wStride, int wBatchStride,
        const float* __restrict__ bias,
        void* __restrict__ OUTv, int oStride){
    extern __shared__ uint32_t smu[];
    uint32_t* xs = smu;
    uint32_t* ws = smu + XS_U;
    float*    sb = (float*)(smu + XS_U + WS_U);
    const int t = threadIdx.x;
    const int warp = t>>5, lane = t&31;
    const int lr = lane>>2, lc = lane&3;
    const int m0 = warp*16;
    const size_t tileBase = (size_t)blockIdx.x*128;
    const float* Wb = W + (wBatchStride ? (int)(tileBase>>16)*(size_t)wBatchStride : 0);
    if(bias && t<64) sb[t] = bias[t];

    float acc[32];
    const int CH = (KC>NC)?KC:NC;

    for(int c=0;c<CH;c++){
        const int kOff = (KC>1)? c*64 : 0;
        const int nOff = (NC>1)? c*64 : 0;
        if(c) __syncthreads();
        if(c==0 || KC>1){
            #pragma unroll
            for(int it=0;it<8;it++){
                int s4 = t + it*256;
                int p = s4>>4, c4 = s4&15;
                float vx,vy,vz,vw;
                if(INBF){
                    const bf16* Xb = (const bf16*)Xv;
                    ld_bf4(Xb + (tileBase+p)*(size_t)xStride + kOff + c4*4, vx,vy,vz,vw);
                } else {
                    const float* Xf = (const float*)Xv;
                    float4 v = *(const float4*)(Xf + (tileBase+p)*(size_t)xStride + kOff + c4*4);
                    vx=v.x; vy=v.y; vz=v.z; vw=v.w;
                }
                uint32_t* xr = xs + p*XS_STRIDE + c4*4;
                xr[0]=tf32c(vx); xr[1]=tf32c(vy); xr[2]=tf32c(vz); xr[3]=tf32c(vw);
            }
        }
        #pragma unroll
        for(int it=0;it<16;it++){
            int s = t + it*256;
            int o = s&63, j = s>>6;
            ws[j*WS_STRIDE+o] = tf32c(Wb[(size_t)(kOff+j)*wStride + nOff + o]);
        }
        __syncthreads();
        if(c==0 || NC>1){
            if(bias){
                #pragma unroll
                for(int j=0;j<8;j++){
                    float b0 = sb[j*8 + 2*lc], b1 = sb[j*8 + 2*lc + 1];
                    acc[j*4+0]=b0; acc[j*4+1]=b1;
                    acc[j*4+2]=b0; acc[j*4+3]=b1;
                }
            } else {
                #pragma unroll
                for(int q=0;q<32;q++) acc[q]=0.f;
            }
        }
        #pragma unroll
        for(int k0=0;k0<64;k0+=8){
            uint32_t a[4];
            const uint32_t* xbp = xs + (m0+lr)*XS_STRIDE + k0 + lc;
            a[0]=xbp[0]; a[1]=xbp[8*XS_STRIDE];
            a[2]=xbp[4]; a[3]=xbp[8*XS_STRIDE+4];
            #pragma unroll
            for(int j=0;j<8;j++){
                uint32_t b0 = ws[(k0+lc  )*WS_STRIDE + j*8 + lr];
                uint32_t b1 = ws[(k0+lc+4)*WS_STRIDE + j*8 + lr];
                MMA_TF32(acc + j*4, a, b0, b1);
            }
        }
        if(NC>1 || c==CH-1){
            #pragma unroll
            for(int j=0;j<8;j++){
                size_t row = tileBase + m0 + lr;
                int col = nOff + j*8 + 2*lc;
                float v0=acc[j*4], v1=acc[j*4+1];
                float v2=acc[j*4+2], v3=acc[j*4+3];
                if(MODE==1){ v0=gelu_f(v0); v1=gelu_f(v1); v2=gelu_f(v2); v3=gelu_f(v3); }
                if(OUTBF){
                    bf16* Ob = (bf16*)OUTv;
                    bf16* p0 = Ob + row*(size_t)oStride + col;
                    bf16* p8 = p0 + 8*(size_t)oStride;
                    bf162 o01 = __float22bfloat162_rn(make_float2(v0,v1));
                    bf162 o23 = __float22bfloat162_rn(make_float2(v2,v3));
                    *(bf162*)p0 = o01;
                    *(bf162*)p8 = o23;
                } else {
                    float* Of = (float*)OUTv;
                    float* p0 = Of + row*(size_t)oStride + col;
                    float* p8 = p0 + 8*(size_t)oStride;
                    if(MODE==2){
                        float2 o0 = *(float2*)p0, o8 = *(float2*)p8;
                        v0+=o0.x; v1+=o0.y; v2+=o8.x; v3+=o8.y;
                    }
                    *(float2*)p0 = make_float2(v0,v1);
                    *(float2*)p8 = make_float2(v2,v3);
                }
            }
        }
    }
}

// ---------------- gram partials via mma tf32 (bf16 inputs) ------------------
#define GR_STRIDE 68
__global__ __launch_bounds__(256) void k_gram(const bf16* __restrict__ Q,
        const bf16* __restrict__ K, float* __restrict__ gpart){
    __shared__ float sq[64*GR_STRIDE], sk[64*GR_STRIDE];
    const int t=threadIdx.x, warp=t>>5, lane=t&31;
    const int lr=lane>>2, lc=lane&3;
    const int b=blockIdx.y;
    const int h = warp&3;
    const int nb = (warp&1)*32;
    float accS[8];
    #pragma unroll
    for(int i=0;i<8;i++) accS[i]=0.f;
    float nrm=0.f;

    for(int ch=0; ch<8; ch++){
        size_t base = ((size_t)b*NPB + (size_t)blockIdx.x*512 + ch*64)*64;
        __syncthreads();
        #pragma unroll
        for(int it=0; it<4; it++){
            int s4 = t + it*256;
            int p = s4>>4, c4 = s4&15;
            float* r = sq + p*GR_STRIDE + c4*4;
            ld_bf4(Q + base + p*64 + c4*4, r[0], r[1], r[2], r[3]);
            float* r2 = sk + p*GR_STRIDE + c4*4;
            ld_bf4(K + base + p*64 + c4*4, r2[0], r2[1], r2[2], r2[3]);
        }
        __syncthreads();
        if(warp<4){
            #pragma unroll
            for(int k0=0;k0<64;k0+=8){
                uint32_t a[4];
                a[0]=tf32c(sk[(k0+lc  )*GR_STRIDE + h*16+lr  ]);
                a[1]=tf32c(sk[(k0+lc  )*GR_STRIDE + h*16+lr+8]);
                a[2]=tf32c(sk[(k0+lc+4)*GR_STRIDE + h*16+lr  ]);
                a[3]=tf32c(sk[(k0+lc+4)*GR_STRIDE + h*16+lr+8]);
                #pragma unroll
                for(int nt=0;nt<2;nt++){
                    uint32_t b0=tf32c(sq[(k0+lc  )*GR_STRIDE + h*16+nt*8+lr]);
                    uint32_t b1=tf32c(sq[(k0+lc+4)*GR_STRIDE + h*16+nt*8+lr]);
                    MMA_TF32(accS+nt*4, a, b0, b1);
                }
            }
        } else {
            const float* s = (warp<6)? sq : sk;
            int c = nb + lane;
            #pragma unroll 8
            for(int p=0;p<64;p++){ float v=s[p*GR_STRIDE+c]; nrm += v*v; }
        }
    }
    float* gp = gpart + ((size_t)b*128 + blockIdx.x)*1152;
    if(warp<4){
        float* gs = gp + h*256;
        #pragma unroll
        for(int nt=0;nt<2;nt++){
            int e0 = nt*8 + 2*lc;
            gs[lr*16 + e0]       = accS[nt*4+0];
            gs[lr*16 + e0+1]     = accS[nt*4+1];
            gs[(lr+8)*16 + e0]   = accS[nt*4+2];
            gs[(lr+8)*16 + e0+1] = accS[nt*4+3];
        }
    } else {
        int off = (warp<6)? 1024 : 1088;
        gp[off + nb + lane] = nrm;
    }
}

// ---------------- attn softmax + fold into Mcomb ---------------------------
__global__ __launch_bounds__(256) void k_attn(const float* __restrict__ gpart,
        const float* __restrict__ Wp, const float* __restrict__ resc,
        float* __restrict__ Mcomb){
    __shared__ float sred[2304];
    __shared__ float sa[2048];
    int tid = threadIdx.x;
    for(int jj=tid;jj<2304;jj+=256){
        int b=jj/1152, j=jj-b*1152;
        float acc=0.f;
        for(int blk=0;blk<128;blk++) acc += gpart[((size_t)b*128+blk)*1152 + j];
        sred[jj]=acc;
    }
    __syncthreads();
    if(tid<128){
        int b=tid>>6, hd=tid&63, h=hd>>4, d=hd&15;
        float nk = fmaxf(sqrtf(sred[b*1152+1088+hd]),1e-6f);
        float r = resc[h];
        float row[16]; float mx=-1e30f;
        #pragma unroll
        for(int e=0;e<16;e++){
            float nq = fmaxf(sqrtf(sred[b*1152+1024+h*16+e]),1e-6f);
            float v = sred[b*1152 + h*256 + d*16 + e] / (nk*nq) * r;
            row[e]=v; mx=fmaxf(mx,v);
        }
        float s=0.f;
        #pragma unroll
        for(int e=0;e<16;e++){ row[e]=expf(row[e]-mx); s+=row[e]; }
        float inv=1.f/s;
        #pragma unroll
        for(int e=0;e<16;e++) sa[((b*4+h)*16+d)*16+e] = row[e]*inv;
    }
    __syncthreads();
    for(int job=tid;job<8192;job+=256){
        int b=job>>12, rem=job&4095, ci=rem>>6, co=rem&63;
        int h=ci>>4, e=ci&15;
        float acc=0.f;
        #pragma unroll
        for(int d=0;d<16;d++) acc += sa[((b*4+h)*16+d)*16+e] * Wp[(h*16+d)*64+co];
        Mcomb[job]=acc;
    }
}

// ---------------- transposes ----------------
__global__ __launch_bounds__(256) void k_nchw2nhwc(const float* __restrict__ in, float* __restrict__ out){
    __shared__ float t[32][33];
    int tx = threadIdx.x & 31, ty = threadIdx.x >> 5;
    int pt = blockIdx.x, ct = blockIdx.y, b = blockIdx.z;
    const float* ip = in  + (size_t)b*64*NPB;
    float*       op = out + (size_t)b*NPB*64;
    #pragma unroll
    for(int r=0;r<4;r++){
        int c = ct*32 + ty + r*8;
        t[ty+r*8][tx] = ip[(size_t)c*NPB + (size_t)pt*32 + tx];
    }
    __syncthreads();
    #pragma unroll
    for(int r=0;r<4;r++){
        int p = pt*32 + ty + r*8;
        op[(size_t)p*64 + ct*32 + tx] = t[tx][ty+r*8];
    }
}
__global__ __launch_bounds__(256) void k_nhwc2nchw(const float* __restrict__ in, float* __restrict__ out){
    __shared__ float t[32][33];
    int tx = threadIdx.x & 31, ty = threadIdx.x >> 5;
    int pt = blockIdx.x, ct = blockIdx.y, b = blockIdx.z;
    const float* ip = in  + (size_t)b*NPB*64;
    float*       op = out + (size_t)b*64*NPB;
    #pragma unroll
    for(int r=0;r<4;r++){
        int p = pt*32 + ty + r*8;
        t[ty+r*8][tx] = ip[(size_t)p*64 + ct*32 + tx];
    }
    __syncthreads();
    #pragma unroll
    for(int r=0;r<4;r++){
        int c = ct*32 + ty + r*8;
        op[(size_t)c*NPB + (size_t)pt*32 + tx] = t[tx][ty+r*8];
    }
}

// ---------------- coalesced LayerNorm (bf16 out) ----------------------------
__global__ __launch_bounds__(256) void k_ln(const float* __restrict__ X,
        const float* __restrict__ g, const float* __restrict__ b,
        bf16* __restrict__ O){
    __shared__ float sx[128*66];
    __shared__ float smu2[128], srs[128];
    int t = threadIdx.x;
    size_t base = (size_t)blockIdx.x * 128;
    for(int s=t;s<4096;s+=256){
        int p = s >> 5, j2 = s & 31;
        float2 v = *(const float2*)(X + (base+p)*64 + j2*2);
        sx[p*66 + j2*2]   = v.x;
        sx[p*66 + j2*2+1] = v.y;
    }
    __syncthreads();
    if(t<128){
        float mu=0.f, m2=0.f;
        const float* r = sx + t*66;
        #pragma unroll 8
        for(int j=0;j<64;j++){ float v=r[j]; mu+=v; m2+=v*v; }
        mu *= (1.f/64.f);
        float var = fmaxf(m2*(1.f/64.f) - mu*mu, 0.f);
        smu2[t]=mu; srs[t]=rsqrtf(var+1e-5f);
    }
    __syncthreads();
    for(int s=t;s<4096;s+=256){
        int p = s >> 5, j2 = s & 31;
        float mu=smu2[p], rs=srs[p];
        int j = j2*2;
        float vx = (sx[p*66+j]  -mu)*rs*g[j]  +b[j];
        float vy = (sx[p*66+j+1]-mu)*rs*g[j+1]+b[j+1];
        bf162 o = __float22bfloat162_rn(make_float2(vx,vy));
        *(bf162*)(O + (base+p)*64 + j) = o;
    }
}

// ---------------- mask gate (bf16 I/O) --------------------------------------
__global__ __launch_bounds__(256) void k_maskgate(const bf16* __restrict__ T,
        const bf16* __restrict__ M1, const bf16* __restrict__ V,
        const float* __restrict__ dw, const float* __restrict__ db,
        bf16* __restrict__ VG){
    __shared__ float4 sdw[400];
    __shared__ float4 sdb4[16];
    int tid=threadIdx.x;
    for(int i=tid;i<400;i+=256) sdw[i]=((const float4*)dw)[i];
    if(tid<16) sdb4[tid]=((const float4*)db)[tid];
    __syncthreads();
    size_t e=(size_t)blockIdx.x*256+tid;
    int c4=(int)(e&15);
    size_t p=e>>4;
    int b=(int)(p>>16);
    int pp=(int)(p&65535);
    int y=pp>>8, x=pp&255;
    float4 conv=make_float4(0,0,0,0);
    #pragma unroll
    for(int dy=0;dy<5;dy++){
        int yy=y+dy-2; if(yy<0||yy>255) continue;
        #pragma unroll
        for(int dx=0;dx<5;dx++){
            int xx=x+dx-2; if(xx<0||xx>255) continue;
            float tx,ty,tz,tw;
            ld_bf4(T + (((((size_t)b<<16)+(yy<<8)+xx)<<6)+c4*4), tx,ty,tz,tw);
            float4 wv = sdw[(dy*5+dx)*16+c4];
            conv.x+=tx*wv.x; conv.y+=ty*wv.y; conv.z+=tz*wv.z; conv.w+=tw*wv.w;
        }
    }
    float4 bb=sdb4[c4];
    float m0,m1v,m2,m3, v0,v1,v2,v3;
    ld_bf4(M1 + e*4, m0,m1v,m2,m3);
    ld_bf4(V  + e*4, v0,v1,v2,v3);
    float r0 = v0*m0*(1.f+1.f/(1.f+expf(-(conv.x+bb.x))));
    float r1 = v1*m1v*(1.f+1.f/(1.f+expf(-(conv.y+bb.y))));
    float r2 = v2*m2*(1.f+1.f/(1.f+expf(-(conv.z+bb.z))));
    float r3 = v3*m3*(1.f+1.f/(1.f+expf(-(conv.w+bb.w))));
    st_bf4(VG + e*4, r0,r1,r2,r3);
}

// ---------------- depthwise 3x3 + GELU, bf16 I/O (C = 1<<cbits) -------------
__global__ __launch_bounds__(256) void k_dw3_gelu_bf(const bf16* __restrict__ in,
        const float* __restrict__ dw, bf16* __restrict__ out, int cbits){
    __shared__ float4 sdw[576];
    int tid=threadIdx.x;
    int C4=1<<(cbits-2);
    for(int i=tid;i<9*C4;i+=256) sdw[i]=((const float4*)dw)[i];
    __syncthreads();
    size_t e=(size_t)blockIdx.x*256+tid;
    int c4=(int)(e&(C4-1));
    size_t p=e>>(cbits-2);
    int b=(int)(p>>16), pp=(int)(p&65535), y=pp>>8, x=pp&255;
    float4 conv=make_float4(0,0,0,0);
    #pragma unroll
    for(int dy=0;dy<3;dy++){
        int yy=y+dy-1; if(yy<0||yy>255) continue;
        #pragma unroll
        for(int dx=0;dx<3;dx++){
            int xx=x+dx-1; if(xx<0||xx>255) continue;
            float tx,ty,tz,tw;
            ld_bf4(in + (((((size_t)b<<16)+(yy<<8)+xx)<<cbits)+c4*4), tx,ty,tz,tw);
            float4 wv = sdw[(dy*3+dx)*C4+c4];
            conv.x+=tx*wv.x; conv.y+=ty*wv.y; conv.z+=tz*wv.z; conv.w+=tw*wv.w;
        }
    }
    st_bf4(out + e*4, gelu_f(conv.x),gelu_f(conv.y),gelu_f(conv.z),gelu_f(conv.w));
}

// ---------------- msa epilogue: X += dw3(P bf16, pe2) -----------------------
__global__ __launch_bounds__(256) void k_msa_out(
        const bf16* __restrict__ P, const float* __restrict__ pe2,
        float* __restrict__ X){
    __shared__ float4 sdw[144];
    int tid=threadIdx.x;
    if(tid<144) sdw[tid]=((const float4*)pe2)[tid];
    __syncthreads();
    size_t e=(size_t)blockIdx.x*256+tid;
    int c4=(int)(e&15);
    size_t p=e>>4;
    int b=(int)(p>>16), pp=(int)(p&65535), y=pp>>8, x=pp&255;
    float4 conv=make_float4(0,0,0,0);
    #pragma unroll
    for(int dy=0;dy<3;dy++){
        int yy=y+dy-1; if(yy<0||yy>255) continue;
        #pragma unroll
        for(int dx=0;dx<3;dx++){
            int xx=x+dx-1; if(xx<0||xx>255) continue;
            float tx,ty,tz,tw;
            ld_bf4(P + (((((size_t)b<<16)+(yy<<8)+xx)<<6)+c4*4), tx,ty,tz,tw);
            float4 wv = sdw[(dy*3+dx)*16+c4];
            conv.x+=tx*wv.x; conv.y+=ty*wv.y; conv.z+=tz*wv.z; conv.w+=tw*wv.w;
        }
    }
    float4 xv=((float4*)X)[e];
    xv.x+=conv.x; xv.y+=conv.y; xv.z+=conv.z; xv.w+=conv.w;
    ((float4*)X)[e]=xv;
}

// ---------------- host -----------------------------------------------------
extern "C" void kernel_launch(void* const* d_in, const int* in_sizes, int n_in,
                              void* d_out, int out_size){
    const float* x    = (const float*)d_in[0];
    const float* mask = (const float*)d_in[1];
    const float* Wq   = (const float*)d_in[2];
    const float* Wk   = (const float*)d_in[3];
    const float* Wv   = (const float*)d_in[4];
    const float* resc = (const float*)d_in[5];
    const float* Wp   = (const float*)d_in[6];
    const float* bp   = (const float*)d_in[7];
    const float* pe1  = (const float*)d_in[8];
    const float* pe2  = (const float*)d_in[9];
    const float* mw1  = (const float*)d_in[10];
    const float* mb1  = (const float*)d_in[11];
    const float* mw2  = (const float*)d_in[12];
    const float* mb2  = (const float*)d_in[13];
    const float* mdw  = (const float*)d_in[14];
    const float* mdb  = (const float*)d_in[15];
    const float* lng  = (const float*)d_in[16];
    const float* lnb  = (const float*)d_in[17];
    const float* fw1  = (const float*)d_in[18];
    const float* fdw  = (const float*)d_in[19];
    const float* fw2  = (const float*)d_in[20];
    float* out = (float*)d_out;

    float *pX,*pM,*pGP,*pMC;
    bf16 *pQ,*pK,*pV,*pT1,*pH1,*pH2;
    cudaGetSymbolAddress((void**)&pX,  g_X);
    cudaGetSymbolAddress((void**)&pM,  g_Mk);
    cudaGetSymbolAddress((void**)&pQ,  g_Q);
    cudaGetSymbolAddress((void**)&pK,  g_K);
    cudaGetSymbolAddress((void**)&pV,  g_V);
    cudaGetSymbolAddress((void**)&pT1, g_T1);
    cudaGetSymbolAddress((void**)&pH1, g_H1);
    cudaGetSymbolAddress((void**)&pH2, g_H2);
    cudaGetSymbolAddress((void**)&pGP, g_GP);
    cudaGetSymbolAddress((void**)&pMC, g_MC);

    cudaFuncSetAttribute(k_tmma<1,1,0,0,1>, cudaFuncAttributeMaxDynamicSharedMemorySize, TM_SMEM);
    cudaFuncSetAttribute(k_tmma<1,1,0,1,1>, cudaFuncAttributeMaxDynamicSharedMemorySize, TM_SMEM);
    cudaFuncSetAttribute(k_tmma<1,1,2,1,0>, cudaFuncAttributeMaxDynamicSharedMemorySize, TM_SMEM);
    cudaFuncSetAttribute(k_tmma<1,4,1,1,1>, cudaFuncAttributeMaxDynamicSharedMemorySize, TM_SMEM);
    cudaFuncSetAttribute(k_tmma<4,1,2,1,0>, cudaFuncAttributeMaxDynamicSharedMemorySize, TM_SMEM);

    dim3 tg(2048,2,2);
    k_nchw2nhwc<<<tg,256>>>(x,    pX);
    k_nchw2nhwc<<<tg,256>>>(mask, pM);

    for(int i=0;i<3;i++){
        const float* Wq_i  = Wq  + i*4096;
        const float* Wk_i  = Wk  + i*4096;
        const float* Wv_i  = Wv  + i*4096;
        const float* Wp_i  = Wp  + i*4096;
        const float* mw1_i = mw1 + i*4096;
        const float* mw2_i = mw2 + i*4096;
        const float* bp_i  = bp  + i*64;
        const float* mb1_i = mb1 + i*64;
        const float* mb2_i = mb2 + i*64;
        const float* mdb_i = mdb + i*64;
        const float* lng_i = lng + i*64;
        const float* lnb_i = lnb + i*64;
        const float* pe1_i = pe1 + i*576;
        const float* pe2_i = pe2 + i*576;
        const float* mdw_i = mdw + i*1600;
        const float* rs_i  = resc+ i*4;
        const float* fw1_i = fw1 + i*64*256;
        const float* fdw_i = fdw + i*9*256;
        const float* fw2_i = fw2 + i*256*64;

        // attention stats path (bf16 Q/K)
        k_tmma<1,1,0,0,1><<<1024,256,TM_SMEM>>>(pX, 64, Wq_i, 64, 0, nullptr, pQ, 64);
        k_tmma<1,1,0,0,1><<<1024,256,TM_SMEM>>>(pX, 64, Wk_i, 64, 0, nullptr, pK, 64);
        k_gram<<<dim3(128,2),256>>>(pQ, pK, pGP);
        k_attn<<<1,256>>>(pGP, Wp_i, rs_i, pMC);
        // v + mask gate (bf16)
        k_tmma<1,1,0,0,1><<<1024,256,TM_SMEM>>>(pX, 64, Wv_i, 64, 0, nullptr, pV, 64);
        k_tmma<1,1,0,0,1><<<1024,256,TM_SMEM>>>(pM, 64, mw1_i, 64, 0, mb1_i, pT1, 64);
        k_tmma<1,1,0,1,1><<<1024,256,TM_SMEM>>>(pT1, 64, mw2_i, 64, 0, mb2_i, pQ, 64);
        k_maskgate<<<8192,256>>>(pQ, pT1, pV, mdw_i, mdb_i, pT1);    // VG -> g_T1
        // positional path (bf16 P)
        k_dw3_gelu_bf<<<8192,256>>>(pV, pe1_i, pK, 6);               // P -> g_K
        // folded attention apply + proj, added straight into X
        k_tmma<1,1,2,1,0><<<1024,256,TM_SMEM>>>(pT1, 64, pMC, 64, 4096, bp_i, pX, 64);
        k_msa_out<<<8192,256>>>(pK, pe2_i, pX);                      // X += dw3(P)
        // feed-forward (bf16 intermediates)
        k_ln<<<1024,256>>>(pX, lng_i, lnb_i, pT1);
        k_tmma<1,4,1,1,1><<<1024,256,TM_SMEM>>>(pT1, 64, fw1_i, 256, 0, nullptr, pH1, 256);
        k_dw3_gelu_bf<<<32768,256>>>(pH1, fdw_i, pH2, 8);
        k_tmma<4,1,2,1,0><<<1024,256,TM_SMEM>>>(pH2, 256, fw2_i, 64, 0, nullptr, pX, 64);
    }

    k_nhwc2nchw<<<tg,256>>>(pX, out);
}

// round 17
// speedup vs baseline: 1.6784x; 1.0360x over previous
#include <cuda_runtime.h>
#include <cuda_bf16.h>
#include <math.h>
#include <stdint.h>

#define NPB 65536
#define NT  131072
typedef __nv_bfloat16 bf16;
typedef __nv_bfloat162 bf162;

// ---------------- scratch ----------
__device__ float g_X [NT*64];
__device__ float g_Mk[NT*64];
__device__ bf16  g_Q [NT*64];
__device__ bf16  g_K [NT*64];
__device__ bf16  g_V [NT*64];
__device__ bf16  g_T1[NT*64];
__device__ bf16  g_H1[NT*256];
__device__ bf16  g_H2[NT*256];
__device__ float g_GP[2*128*1152];
__device__ float g_MC[2*64*64];

__device__ __forceinline__ float gelu_f(float u){
    return 0.5f*u*(1.f+erff(u*0.70710678118654752f));
}
__device__ __forceinline__ uint32_t tf32c(float f){
    uint32_t r; asm("cvt.rna.tf32.f32 %0, %1;" : "=r"(r) : "f"(f)); return r;
}
__device__ __forceinline__ void ld_bf4(const bf16* p, float&a, float&b, float&c, float&d){
    uint2 raw = *(const uint2*)p;
    float2 f01 = __bfloat1622float2(*reinterpret_cast<bf162*>(&raw.x));
    float2 f23 = __bfloat1622float2(*reinterpret_cast<bf162*>(&raw.y));
    a=f01.x; b=f01.y; c=f23.x; d=f23.y;
}
__device__ __forceinline__ void st_bf4(bf16* p, float a, float b, float c, float d){
    uint2 r;
    bf162 o01 = __float22bfloat162_rn(make_float2(a,b));
    bf162 o23 = __float22bfloat162_rn(make_float2(c,d));
    r.x = *reinterpret_cast<uint32_t*>(&o01);
    r.y = *reinterpret_cast<uint32_t*>(&o23);
    *(uint2*)p = r;
}
#define MMA_TF32(d, a, b0, b1) \
  asm volatile("mma.sync.aligned.m16n8k8.row.col.f32.tf32.tf32.f32 " \
    "{%0,%1,%2,%3},{%4,%5,%6,%7},{%8,%9},{%0,%1,%2,%3};" \
    : "+f"((d)[0]),"+f"((d)[1]),"+f"((d)[2]),"+f"((d)[3]) \
    : "r"((a)[0]),"r"((a)[1]),"r"((a)[2]),"r"((a)[3]),"r"(b0),"r"(b1))
#define MMA_BF16(d, a, b0, b1) \
  asm volatile("mma.sync.aligned.m16n8k16.row.col.f32.bf16.bf16.f32 " \
    "{%0,%1,%2,%3},{%4,%5,%6,%7},{%8,%9},{%0,%1,%2,%3};" \
    : "+f"((d)[0]),"+f"((d)[1]),"+f"((d)[2]),"+f"((d)[3]) \
    : "r"((a)[0]),"r"((a)[1]),"r"((a)[2]),"r"((a)[3]),"r"(b0),"r"(b1))

// ---------------- bf16 tensor GEMM, 256-thread ------------------------------
// Tile 128px(M) x 64out(N), K=64/chunk, mma.m16n8k16.bf16.
// xs: [128 px][72] bf16 (a-frags conflict-free); ws: [64 n][68] bf16 (k-major rows).
#define XSB 72
#define WSB 68
#define TM_SMEM (128*XSB*2 + 64*WSB*2 + 256)

template<int KC,int NC,int MODE,int INBF,int OUTBF>
__global__ __launch_bounds__(256, 3) void k_tmma(
        const void* __restrict__ Xv, int xStride,
        const float* __restrict__ W, int wStride, int wBatchStride,
        const float* __restrict__ bias,
        void* __restrict__ OUTv, int oStride){
    extern __shared__ char smc[];
    bf16* xs = (bf16*)smc;
    bf16* ws = xs + 128*XSB;
    float* sb = (float*)(smc + 128*XSB*2 + 64*WSB*2);
    const int t = threadIdx.x;
    const int warp = t>>5, lane = t&31;
    const int lr = lane>>2, lc = lane&3;
    const int m0 = warp*16;
    const size_t tileBase = (size_t)blockIdx.x*128;
    const float* Wb = W + (wBatchStride ? (int)(tileBase>>16)*(size_t)wBatchStride : 0);
    if(bias && t<64) sb[t] = bias[t];

    float acc[32];
    const int CH = (KC>NC)?KC:NC;

    for(int c=0;c<CH;c++){
        const int kOff = (KC>1)? c*64 : 0;
        const int nOff = (NC>1)? c*64 : 0;
        if(c) __syncthreads();
        if(c==0 || KC>1){
            #pragma unroll
            for(int it=0;it<8;it++){
                int s4 = t + it*256;
                int p = s4>>4, c4 = s4&15;
                if(INBF){
                    const bf16* Xb = (const bf16*)Xv;
                    uint2 raw = *(const uint2*)(Xb + (tileBase+p)*(size_t)xStride + kOff + c4*4);
                    *(uint2*)(xs + p*XSB + c4*4) = raw;
                } else {
                    const float* Xf = (const float*)Xv;
                    float4 v = *(const float4*)(Xf + (tileBase+p)*(size_t)xStride + kOff + c4*4);
                    st_bf4(xs + p*XSB + c4*4, v.x, v.y, v.z, v.w);
                }
            }
        }
        // ws[n][k] = W[kOff+k][nOff+n], bf16
        #pragma unroll
        for(int it=0;it<16;it++){
            int s = t + it*256;
            int o = s&63, j = s>>6;
            ws[o*WSB + j] = __float2bfloat16_rn(Wb[(size_t)(kOff+j)*wStride + nOff + o]);
        }
        __syncthreads();
        if(c==0 || NC>1){
            if(bias){
                #pragma unroll
                for(int j=0;j<8;j++){
                    float b0 = sb[j*8 + 2*lc], b1 = sb[j*8 + 2*lc + 1];
                    acc[j*4+0]=b0; acc[j*4+1]=b1;
                    acc[j*4+2]=b0; acc[j*4+3]=b1;
                }
            } else {
                #pragma unroll
                for(int q=0;q<32;q++) acc[q]=0.f;
            }
        }
        const uint32_t* xw32 = (const uint32_t*)xs;
        const uint32_t* ww32 = (const uint32_t*)ws;
        #pragma unroll
        for(int k0=0;k0<64;k0+=16){
            uint32_t a[4];
            const uint32_t* xw = xw32 + (m0+lr)*(XSB/2) + (k0>>1) + lc;
            a[0]=xw[0]; a[1]=xw[8*(XSB/2)];
            a[2]=xw[4]; a[3]=xw[8*(XSB/2)+4];
            #pragma unroll
            for(int j=0;j<8;j++){
                const uint32_t* wwp = ww32 + (j*8+lr)*(WSB/2) + (k0>>1) + lc;
                uint32_t b0 = wwp[0];
                uint32_t b1 = wwp[4];
                MMA_BF16(acc + j*4, a, b0, b1);
            }
        }
        if(NC>1 || c==CH-1){
            #pragma unroll
            for(int j=0;j<8;j++){
                size_t row = tileBase + m0 + lr;
                int col = nOff + j*8 + 2*lc;
                float v0=acc[j*4], v1=acc[j*4+1];
                float v2=acc[j*4+2], v3=acc[j*4+3];
                if(MODE==1){ v0=gelu_f(v0); v1=gelu_f(v1); v2=gelu_f(v2); v3=gelu_f(v3); }
                if(OUTBF){
                    bf16* Ob = (bf16*)OUTv;
                    bf16* p0 = Ob + row*(size_t)oStride + col;
                    bf16* p8 = p0 + 8*(size_t)oStride;
                    *(bf162*)p0 = __float22bfloat162_rn(make_float2(v0,v1));
                    *(bf162*)p8 = __float22bfloat162_rn(make_float2(v2,v3));
                } else {
                    float* Of = (float*)OUTv;
                    float* p0 = Of + row*(size_t)oStride + col;
                    float* p8 = p0 + 8*(size_t)oStride;
                    if(MODE==2){
                        float2 o0 = *(float2*)p0, o8 = *(float2*)p8;
                        v0+=o0.x; v1+=o0.y; v2+=o8.x; v3+=o8.y;
                    }
                    *(float2*)p0 = make_float2(v0,v1);
                    *(float2*)p8 = make_float2(v2,v3);
                }
            }
        }
    }
}

// ---------------- gram partials via mma tf32 (bf16 inputs) ------------------
#define GR_STRIDE 68
__global__ __launch_bounds__(256) void k_gram(const bf16* __restrict__ Q,
        const bf16* __restrict__ K, float* __restrict__ gpart){
    __shared__ float sq[64*GR_STRIDE], sk[64*GR_STRIDE];
    const int t=threadIdx.x, warp=t>>5, lane=t&31;
    const int lr=lane>>2, lc=lane&3;
    const int b=blockIdx.y;
    const int h = warp&3;
    const int nb = (warp&1)*32;
    float accS[8];
    #pragma unroll
    for(int i=0;i<8;i++) accS[i]=0.f;
    float nrm=0.f;

    for(int ch=0; ch<8; ch++){
        size_t base = ((size_t)b*NPB + (size_t)blockIdx.x*512 + ch*64)*64;
        __syncthreads();
        #pragma unroll
        for(int it=0; it<4; it++){
            int s4 = t + it*256;
            int p = s4>>4, c4 = s4&15;
            float* r = sq + p*GR_STRIDE + c4*4;
            ld_bf4(Q + base + p*64 + c4*4, r[0], r[1], r[2], r[3]);
            float* r2 = sk + p*GR_STRIDE + c4*4;
            ld_bf4(K + base + p*64 + c4*4, r2[0], r2[1], r2[2], r2[3]);
        }
        __syncthreads();
        if(warp<4){
            #pragma unroll
            for(int k0=0;k0<64;k0+=8){
                uint32_t a[4];
                a[0]=tf32c(sk[(k0+lc  )*GR_STRIDE + h*16+lr  ]);
                a[1]=tf32c(sk[(k0+lc  )*GR_STRIDE + h*16+lr+8]);
                a[2]=tf32c(sk[(k0+lc+4)*GR_STRIDE + h*16+lr  ]);
                a[3]=tf32c(sk[(k0+lc+4)*GR_STRIDE + h*16+lr+8]);
                #pragma unroll
                for(int nt=0;nt<2;nt++){
                    uint32_t b0=tf32c(sq[(k0+lc  )*GR_STRIDE + h*16+nt*8+lr]);
                    uint32_t b1=tf32c(sq[(k0+lc+4)*GR_STRIDE + h*16+nt*8+lr]);
                    MMA_TF32(accS+nt*4, a, b0, b1);
                }
            }
        } else {
            const float* s = (warp<6)? sq : sk;
            int c = nb + lane;
            #pragma unroll 8
            for(int p=0;p<64;p++){ float v=s[p*GR_STRIDE+c]; nrm += v*v; }
        }
    }
    float* gp = gpart + ((size_t)b*128 + blockIdx.x)*1152;
    if(warp<4){
        float* gs = gp + h*256;
        #pragma unroll
        for(int nt=0;nt<2;nt++){
            int e0 = nt*8 + 2*lc;
            gs[lr*16 + e0]       = accS[nt*4+0];
            gs[lr*16 + e0+1]     = accS[nt*4+1];
            gs[(lr+8)*16 + e0]   = accS[nt*4+2];
            gs[(lr+8)*16 + e0+1] = accS[nt*4+3];
        }
    } else {
        int off = (warp<6)? 1024 : 1088;
        gp[off + nb + lane] = nrm;
    }
}

// ---------------- attn softmax + fold into Mcomb ---------------------------
__global__ __launch_bounds__(256) void k_attn(const float* __restrict__ gpart,
        const float* __restrict__ Wp, const float* __restrict__ resc,
        float* __restrict__ Mcomb){
    __shared__ float sred[2304];
    __shared__ float sa[2048];
    int tid = threadIdx.x;
    for(int jj=tid;jj<2304;jj+=256){
        int b=jj/1152, j=jj-b*1152;
        float acc=0.f;
        for(int blk=0;blk<128;blk++) acc += gpart[((size_t)b*128+blk)*1152 + j];
        sred[jj]=acc;
    }
    __syncthreads();
    if(tid<128){
        int b=tid>>6, hd=tid&63, h=hd>>4, d=hd&15;
        float nk = fmaxf(sqrtf(sred[b*1152+1088+hd]),1e-6f);
        float r = resc[h];
        float row[16]; float mx=-1e30f;
        #pragma unroll
        for(int e=0;e<16;e++){
            float nq = fmaxf(sqrtf(sred[b*1152+1024+h*16+e]),1e-6f);
            float v = sred[b*1152 + h*256 + d*16 + e] / (nk*nq) * r;
            row[e]=v; mx=fmaxf(mx,v);
        }
        float s=0.f;
        #pragma unroll
        for(int e=0;e<16;e++){ row[e]=expf(row[e]-mx); s+=row[e]; }
        float inv=1.f/s;
        #pragma unroll
        for(int e=0;e<16;e++) sa[((b*4+h)*16+d)*16+e] = row[e]*inv;
    }
    __syncthreads();
    for(int job=tid;job<8192;job+=256){
        int b=job>>12, rem=job&4095, ci=rem>>6, co=rem&63;
        int h=ci>>4, e=ci&15;
        float acc=0.f;
        #pragma unroll
        for(int d=0;d<16;d++) acc += sa[((b*4+h)*16+d)*16+e] * Wp[(h*16+d)*64+co];
        Mcomb[job]=acc;
    }
}

// ---------------- transposes ----------------
__global__ __launch_bounds__(256) void k_nchw2nhwc(const float* __restrict__ in, float* __restrict__ out){
    __shared__ float t[32][33];
    int tx = threadIdx.x & 31, ty = threadIdx.x >> 5;
    int pt = blockIdx.x, ct = blockIdx.y, b = blockIdx.z;
    const float* ip = in  + (size_t)b*64*NPB;
    float*       op = out + (size_t)b*NPB*64;
    #pragma unroll
    for(int r=0;r<4;r++){
        int c = ct*32 + ty + r*8;
        t[ty+r*8][tx] = ip[(size_t)c*NPB + (size_t)pt*32 + tx];
    }
    __syncthreads();
    #pragma unroll
    for(int r=0;r<4;r++){
        int p = pt*32 + ty + r*8;
        op[(size_t)p*64 + ct*32 + tx] = t[tx][ty+r*8];
    }
}
__global__ __launch_bounds__(256) void k_nhwc2nchw(const float* __restrict__ in, float* __restrict__ out){
    __shared__ float t[32][33];
    int tx = threadIdx.x & 31, ty = threadIdx.x >> 5;
    int pt = blockIdx.x, ct = blockIdx.y, b = blockIdx.z;
    const float* ip = in  + (size_t)b*NPB*64;
    float*       op = out + (size_t)b*64*NPB;
    #pragma unroll
    for(int r=0;r<4;r++){
        int p = pt*32 + ty + r*8;
        t[ty+r*8][tx] = ip[(size_t)p*64 + ct*32 + tx];
    }
    __syncthreads();
    #pragma unroll
    for(int r=0;r<4;r++){
        int c = ct*32 + ty + r*8;
        op[(size_t)c*NPB + (size_t)pt*32 + tx] = t[tx][ty+r*8];
    }
}

// ---------------- coalesced LayerNorm (bf16 out) ----------------------------
__global__ __launch_bounds__(256) void k_ln(const float* __restrict__ X,
        const float* __restrict__ g, const float* __restrict__ b,
        bf16* __restrict__ O){
    __shared__ float sx[128*66];
    __shared__ float smu2[128], srs[128];
    int t = threadIdx.x;
    size_t base = (size_t)blockIdx.x * 128;
    for(int s=t;s<4096;s+=256){
        int p = s >> 5, j2 = s & 31;
        float2 v = *(const float2*)(X + (base+p)*64 + j2*2);
        sx[p*66 + j2*2]   = v.x;
        sx[p*66 + j2*2+1] = v.y;
    }
    __syncthreads();
    if(t<128){
        float mu=0.f, m2=0.f;
        const float* r = sx + t*66;
        #pragma unroll 8
        for(int j=0;j<64;j++){ float v=r[j]; mu+=v; m2+=v*v; }
        mu *= (1.f/64.f);
        float var = fmaxf(m2*(1.f/64.f) - mu*mu, 0.f);
        smu2[t]=mu; srs[t]=rsqrtf(var+1e-5f);
    }
    __syncthreads();
    for(int s=t;s<4096;s+=256){
        int p = s >> 5, j2 = s & 31;
        float mu=smu2[p], rs=srs[p];
        int j = j2*2;
        float vx = (sx[p*66+j]  -mu)*rs*g[j]  +b[j];
        float vy = (sx[p*66+j+1]-mu)*rs*g[j+1]+b[j+1];
        bf162 o = __float22bfloat162_rn(make_float2(vx,vy));
        *(bf162*)(O + (base+p)*64 + j) = o;
    }
}

// ---------------- mask gate (bf16 I/O) --------------------------------------
__global__ __launch_bounds__(256) void k_maskgate(const bf16* __restrict__ T,
        const bf16* __restrict__ M1, const bf16* __restrict__ V,
        const float* __restrict__ dw, const float* __restrict__ db,
        bf16* __restrict__ VG){
    __shared__ float4 sdw[400];
    __shared__ float4 sdb4[16];
    int tid=threadIdx.x;
    for(int i=tid;i<400;i+=256) sdw[i]=((const float4*)dw)[i];
    if(tid<16) sdb4[tid]=((const float4*)db)[tid];
    __syncthreads();
    size_t e=(size_t)blockIdx.x*256+tid;
    int c4=(int)(e&15);
    size_t p=e>>4;
    int b=(int)(p>>16);
    int pp=(int)(p&65535);
    int y=pp>>8, x=pp&255;
    float4 conv=make_float4(0,0,0,0);
    #pragma unroll
    for(int dy=0;dy<5;dy++){
        int yy=y+dy-2; if(yy<0||yy>255) continue;
        #pragma unroll
        for(int dx=0;dx<5;dx++){
            int xx=x+dx-2; if(xx<0||xx>255) continue;
            float tx,ty,tz,tw;
            ld_bf4(T + (((((size_t)b<<16)+(yy<<8)+xx)<<6)+c4*4), tx,ty,tz,tw);
            float4 wv = sdw[(dy*5+dx)*16+c4];
            conv.x+=tx*wv.x; conv.y+=ty*wv.y; conv.z+=tz*wv.z; conv.w+=tw*wv.w;
        }
    }
    float4 bb=sdb4[c4];
    float m0,m1v,m2,m3, v0,v1,v2,v3;
    ld_bf4(M1 + e*4, m0,m1v,m2,m3);
    ld_bf4(V  + e*4, v0,v1,v2,v3);
    float r0 = v0*m0*(1.f+1.f/(1.f+expf(-(conv.x+bb.x))));
    float r1 = v1*m1v*(1.f+1.f/(1.f+expf(-(conv.y+bb.y))));
    float r2 = v2*m2*(1.f+1.f/(1.f+expf(-(conv.z+bb.z))));
    float r3 = v3*m3*(1.f+1.f/(1.f+expf(-(conv.w+bb.w))));
    st_bf4(VG + e*4, r0,r1,r2,r3);
}

// ---------------- depthwise 3x3 + GELU, bf16 I/O (C = 1<<cbits) -------------
__global__ __launch_bounds__(256) void k_dw3_gelu_bf(const bf16* __restrict__ in,
        const float* __restrict__ dw, bf16* __restrict__ out, int cbits){
    __shared__ float4 sdw[576];
    int tid=threadIdx.x;
    int C4=1<<(cbits-2);
    for(int i=tid;i<9*C4;i+=256) sdw[i]=((const float4*)dw)[i];
    __syncthreads();
    size_t e=(size_t)blockIdx.x*256+tid;
    int c4=(int)(e&(C4-1));
    size_t p=e>>(cbits-2);
    int b=(int)(p>>16), pp=(int)(p&65535), y=pp>>8, x=pp&255;
    float4 conv=make_float4(0,0,0,0);
    #pragma unroll
    for(int dy=0;dy<3;dy++){
        int yy=y+dy-1; if(yy<0||yy>255) continue;
        #pragma unroll
        for(int dx=0;dx<3;dx++){
            int xx=x+dx-1; if(xx<0||xx>255) continue;
            float tx,ty,tz,tw;
            ld_bf4(in + (((((size_t)b<<16)+(yy<<8)+xx)<<cbits)+c4*4), tx,ty,tz,tw);
            float4 wv = sdw[(dy*3+dx)*C4+c4];
            conv.x+=tx*wv.x; conv.y+=ty*wv.y; conv.z+=tz*wv.z; conv.w+=tw*wv.w;
        }
    }
    st_bf4(out + e*4, gelu_f(conv.x),gelu_f(conv.y),gelu_f(conv.z),gelu_f(conv.w));
}

// ---------------- msa epilogue: X += dw3(P bf16, pe2) -----------------------
__global__ __launch_bounds__(256) void k_msa_out(
        const bf16* __restrict__ P, const float* __restrict__ pe2,
        float* __restrict__ X){
    __shared__ float4 sdw[144];
    int tid=threadIdx.x;
    if(tid<144) sdw[tid]=((const float4*)pe2)[tid];
    __syncthreads();
    size_t e=(size_t)blockIdx.x*256+tid;
    int c4=(int)(e&15);
    size_t p=e>>4;
    int b=(int)(p>>16), pp=(int)(p&65535), y=pp>>8, x=pp&255;
    float4 conv=make_float4(0,0,0,0);
    #pragma unroll
    for(int dy=0;dy<3;dy++){
        int yy=y+dy-1; if(yy<0||yy>255) continue;
        #pragma unroll
        for(int dx=0;dx<3;dx++){
            int xx=x+dx-1; if(xx<0||xx>255) continue;
            float tx,ty,tz,tw;
            ld_bf4(P + (((((size_t)b<<16)+(yy<<8)+xx)<<6)+c4*4), tx,ty,tz,tw);
            float4 wv = sdw[(dy*3+dx)*16+c4];
            conv.x+=tx*wv.x; conv.y+=ty*wv.y; conv.z+=tz*wv.z; conv.w+=tw*wv.w;
        }
    }
    float4 xv=((float4*)X)[e];
    xv.x+=conv.x; xv.y+=conv.y; xv.z+=conv.z; xv.w+=conv.w;
    ((float4*)X)[e]=xv;
}

// ---------------- host -----------------------------------------------------
extern "C" void kernel_launch(void* const* d_in, const int* in_sizes, int n_in,
                              void* d_out, int out_size){
    const float* x    = (const float*)d_in[0];
    const float* mask = (const float*)d_in[1];
    const float* Wq   = (const float*)d_in[2];
    const float* Wk   = (const float*)d_in[3];
    const float* Wv   = (const float*)d_in[4];
    const float* resc = (const float*)d_in[5];
    const float* Wp   = (const float*)d_in[6];
    const float* bp   = (const float*)d_in[7];
    const float* pe1  = (const float*)d_in[8];
    const float* pe2  = (const float*)d_in[9];
    const float* mw1  = (const float*)d_in[10];
    const float* mb1  = (const float*)d_in[11];
    const float* mw2  = (const float*)d_in[12];
    const float* mb2  = (const float*)d_in[13];
    const float* mdw  = (const float*)d_in[14];
    const float* mdb  = (const float*)d_in[15];
    const float* lng  = (const float*)d_in[16];
    const float* lnb  = (const float*)d_in[17];
    const float* fw1  = (const float*)d_in[18];
    const float* fdw  = (const float*)d_in[19];
    const float* fw2  = (const float*)d_in[20];
    float* out = (float*)d_out;

    float *pX,*pM,*pGP,*pMC;
    bf16 *pQ,*pK,*pV,*pT1,*pH1,*pH2;
    cudaGetSymbolAddress((void**)&pX,  g_X);
    cudaGetSymbolAddress((void**)&pM,  g_Mk);
    cudaGetSymbolAddress((void**)&pQ,  g_Q);
    cudaGetSymbolAddress((void**)&pK,  g_K);
    cudaGetSymbolAddress((void**)&pV,  g_V);
    cudaGetSymbolAddress((void**)&pT1, g_T1);
    cudaGetSymbolAddress((void**)&pH1, g_H1);
    cudaGetSymbolAddress((void**)&pH2, g_H2);
    cudaGetSymbolAddress((void**)&pGP, g_GP);
    cudaGetSymbolAddress((void**)&pMC, g_MC);

    cudaFuncSetAttribute(k_tmma<1,1,0,0,1>, cudaFuncAttributeMaxDynamicSharedMemorySize, TM_SMEM);
    cudaFuncSetAttribute(k_tmma<1,1,0,1,1>, cudaFuncAttributeMaxDynamicSharedMemorySize, TM_SMEM);
    cudaFuncSetAttribute(k_tmma<1,1,2,1,0>, cudaFuncAttributeMaxDynamicSharedMemorySize, TM_SMEM);
    cudaFuncSetAttribute(k_tmma<1,4,1,1,1>, cudaFuncAttributeMaxDynamicSharedMemorySize, TM_SMEM);
    cudaFuncSetAttribute(k_tmma<4,1,2,1,0>, cudaFuncAttributeMaxDynamicSharedMemorySize, TM_SMEM);

    dim3 tg(2048,2,2);
    k_nchw2nhwc<<<tg,256>>>(x,    pX);
    k_nchw2nhwc<<<tg,256>>>(mask, pM);

    for(int i=0;i<3;i++){
        const float* Wq_i  = Wq  + i*4096;
        const float* Wk_i  = Wk  + i*4096;
        const float* Wv_i  = Wv  + i*4096;
        const float* Wp_i  = Wp  + i*4096;
        const float* mw1_i = mw1 + i*4096;
        const float* mw2_i = mw2 + i*4096;
        const float* bp_i  = bp  + i*64;
        const float* mb1_i = mb1 + i*64;
        const float* mb2_i = mb2 + i*64;
        const float* mdb_i = mdb + i*64;
        const float* lng_i = lng + i*64;
        const float* lnb_i = lnb + i*64;
        const float* pe1_i = pe1 + i*576;
        const float* pe2_i = pe2 + i*576;
        const float* mdw_i = mdw + i*1600;
        const float* rs_i  = resc+ i*4;
        const float* fw1_i = fw1 + i*64*256;
        const float* fdw_i = fdw + i*9*256;
        const float* fw2_i = fw2 + i*256*64;

        // attention stats path (bf16 Q/K)
        k_tmma<1,1,0,0,1><<<1024,256,TM_SMEM>>>(pX, 64, Wq_i, 64, 0, nullptr, pQ, 64);
        k_tmma<1,1,0,0,1><<<1024,256,TM_SMEM>>>(pX, 64, Wk_i, 64, 0, nullptr, pK, 64);
        k_gram<<<dim3(128,2),256>>>(pQ, pK, pGP);
        k_attn<<<1,256>>>(pGP, Wp_i, rs_i, pMC);
        // v + mask gate (bf16)
        k_tmma<1,1,0,0,1><<<1024,256,TM_SMEM>>>(pX, 64, Wv_i, 64, 0, nullptr, pV, 64);
        k_tmma<1,1,0,0,1><<<1024,256,TM_SMEM>>>(pM, 64, mw1_i, 64, 0, mb1_i, pT1, 64);
        k_tmma<1,1,0,1,1><<<1024,256,TM_SMEM>>>(pT1, 64, mw2_i, 64, 0, mb2_i, pQ, 64);
        k_maskgate<<<8192,256>>>(pQ, pT1, pV, mdw_i, mdb_i, pT1);    // VG -> g_T1
        // positional path (bf16 P)
        k_dw3_gelu_bf<<<8192,256>>>(pV, pe1_i, pK, 6);               // P -> g_K
        // folded attention apply + proj, added straight into X
        k_tmma<1,1,2,1,0><<<1024,256,TM_SMEM>>>(pT1, 64, pMC, 64, 4096, bp_i, pX, 64);
        k_msa_out<<<8192,256>>>(pK, pe2_i, pX);                      // X += dw3(P)
        // feed-forward (bf16 intermediates)
        k_ln<<<1024,256>>>(pX, lng_i, lnb_i, pT1);
        k_tmma<1,4,1,1,1><<<1024,256,TM_SMEM>>>(pT1, 64, fw1_i, 256, 0, nullptr, pH1, 256);
        k_dw3_gelu_bf<<<32768,256>>>(pH1, fdw_i, pH2, 8);
        k_tmma<4,1,2,1,0><<<1024,256,TM_SMEM>>>(pH2, 256, fw2_i, 64, 0, nullptr, pX, 64);
    }

    k_nhwc2nchw<<<tg,256>>>(pX, out);
}